// round 1
// baseline (speedup 1.0000x reference)
#include <cuda_runtime.h>

typedef unsigned long long ull;

#define T_TOK 4096
#define DIM   1024
#define HID   2048
#define NEXP  8
#define NP    (T_TOK * 2)          // (token, slot) pairs
#define BM    128
#define MAXTILES (NP / BM + NEXP)  // 72 upper bound on row tiles

// ---------------- scratch (device globals; no allocation allowed) ----------
__device__ int   g_pair[NP];        // sorted row -> pair index (token*2+slot)
__device__ int   g_pos[NP];         // pair index -> sorted row
__device__ float g_gate[NP];
__device__ int   g_expert[NP];
__device__ int   g_counts[NEXP];
__device__ int   g_fill[NEXP];
__device__ int   g_offs[NEXP + 1];
__device__ int   g_tile_e[MAXTILES];
__device__ int   g_tile_r0[MAXTILES];
__device__ int   g_tile_rows[MAXTILES];
__device__ int   g_ntiles;
__device__ float g_H[(size_t)NP * HID];   // 64 MB: hidden activations
__device__ float g_P[(size_t)NP * DIM];   // 32 MB: per-pair expert outputs

// ---------------- packed fp32 helpers (fma.rn.f32x2, sm_100+) --------------
__device__ __forceinline__ ull pack2(float x, float y) {
    ull r;
    asm("mov.b64 %0, {%1, %2};" : "=l"(r) : "f"(x), "f"(y));
    return r;
}
__device__ __forceinline__ void unpack2(ull v, float& x, float& y) {
    asm("mov.b64 {%0, %1}, %2;" : "=f"(x), "=f"(y) : "l"(v));
}
__device__ __forceinline__ ull fma2(ull a, ull b, ull c) {
    ull d;
    asm("fma.rn.f32x2 %0, %1, %2, %3;" : "=l"(d) : "l"(a), "l"(b), "l"(c));
    return d;
}

// ---------------- kernels ---------------------------------------------------

__global__ void init_kernel() {
    int t = threadIdx.x;
    if (t < NEXP) { g_counts[t] = 0; g_fill[t] = 0; }
}

// one warp per token: logits, softmax-top2, renormalized gates
__global__ void router_kernel(const float* __restrict__ x,
                              const float* __restrict__ Wr) {
    int warp = (blockIdx.x * blockDim.x + threadIdx.x) >> 5;
    int lane = threadIdx.x & 31;
    if (warp >= T_TOK) return;
    const float* xr = x + (size_t)warp * DIM;
    float acc[NEXP];
#pragma unroll
    for (int e = 0; e < NEXP; e++) acc[e] = 0.f;
    for (int d = lane; d < DIM; d += 32) {
        float xv = xr[d];
        const float4* w = reinterpret_cast<const float4*>(Wr + (size_t)d * NEXP);
        float4 w0 = w[0], w1 = w[1];
        acc[0] = fmaf(xv, w0.x, acc[0]); acc[1] = fmaf(xv, w0.y, acc[1]);
        acc[2] = fmaf(xv, w0.z, acc[2]); acc[3] = fmaf(xv, w0.w, acc[3]);
        acc[4] = fmaf(xv, w1.x, acc[4]); acc[5] = fmaf(xv, w1.y, acc[5]);
        acc[6] = fmaf(xv, w1.z, acc[6]); acc[7] = fmaf(xv, w1.w, acc[7]);
    }
#pragma unroll
    for (int off = 16; off > 0; off >>= 1) {
#pragma unroll
        for (int e = 0; e < NEXP; e++)
            acc[e] += __shfl_down_sync(0xffffffffu, acc[e], off);
    }
    if (lane == 0) {
        int i0 = 0;
        float m0 = acc[0];
#pragma unroll
        for (int e = 1; e < NEXP; e++)
            if (acc[e] > m0) { m0 = acc[e]; i0 = e; }
        int i1 = -1;
        float m1 = -3.4e38f;
#pragma unroll
        for (int e = 0; e < NEXP; e++)
            if (e != i0 && acc[e] > m1) { m1 = acc[e]; i1 = e; }
        // softmax + top2 + renorm collapses to a 2-way sigmoid of the logit gap
        float g0 = 1.f / (1.f + expf(m1 - m0));
        int p0 = warp * 2, p1 = p0 + 1;
        g_expert[p0] = i0; g_gate[p0] = g0;
        g_expert[p1] = i1; g_gate[p1] = 1.f - g0;
        atomicAdd(&g_counts[i0], 1);
        atomicAdd(&g_counts[i1], 1);
    }
}

// single thread: prefix offsets + row-tile table
__global__ void scan_kernel() {
    int off = 0;
    for (int e = 0; e < NEXP; e++) { g_offs[e] = off; off += g_counts[e]; }
    g_offs[NEXP] = off;
    int nt = 0;
    for (int e = 0; e < NEXP; e++) {
        int c = g_counts[e], base = g_offs[e];
        for (int r = 0; r < c; r += BM) {
            g_tile_e[nt]    = e;
            g_tile_r0[nt]   = base + r;
            g_tile_rows[nt] = (c - r < BM) ? (c - r) : BM;
            nt++;
        }
    }
    g_ntiles = nt;
}

__global__ void scatter_kernel() {
    int p = blockIdx.x * blockDim.x + threadIdx.x;
    if (p >= NP) return;
    int e = g_expert[p];
    int row = g_offs[e] + atomicAdd(&g_fill[e], 1);
    g_pair[p >= 0 ? row : 0] = p;
    g_pos[p] = row;
}

// GEMM1: H[row, n] = silu(x@W1) * (x@W3), per expert tile [128 x 64] x2 mats
__global__ __launch_bounds__(256, 2)
void gemm1_kernel(const float* __restrict__ x,
                  const float* __restrict__ W1,
                  const float* __restrict__ W3) {
    if ((int)blockIdx.x >= g_ntiles) return;
    int e    = g_tile_e[blockIdx.x];
    int row0 = g_tile_r0[blockIdx.x];
    int rows = g_tile_rows[blockIdx.x];
    int n0   = blockIdx.y * 64;
    const float* W1e = W1 + (size_t)e * DIM * HID;
    const float* W3e = W3 + (size_t)e * DIM * HID;

    __shared__ __align__(16) float As[16][128];
    __shared__ __align__(16) float B1s[16][64];
    __shared__ __align__(16) float B3s[16][64];
    __shared__ int s_tok[128];

    int tid = threadIdx.x;
    if (tid < 128)
        s_tok[tid] = (tid < rows) ? (g_pair[row0 + tid] >> 1) : -1;
    __syncthreads();

    ull c1[8][2], c3[8][2];
#pragma unroll
    for (int i = 0; i < 8; i++) {
        c1[i][0] = c1[i][1] = 0ull;
        c3[i][0] = c3[i][1] = 0ull;
    }
    int ty = tid >> 4, tx = tid & 15;

    for (int k0 = 0; k0 < DIM; k0 += 16) {
        // A: gathered token rows, 2 float4 per thread
#pragma unroll
        for (int p = 0; p < 2; p++) {
            int idx = p * 256 + tid;
            int r = idx >> 2, kq = (idx & 3) << 2;
            int tok = s_tok[r];
            float4 v = make_float4(0.f, 0.f, 0.f, 0.f);
            if (tok >= 0)
                v = *reinterpret_cast<const float4*>(x + (size_t)tok * DIM + k0 + kq);
            As[kq + 0][r] = v.x; As[kq + 1][r] = v.y;
            As[kq + 2][r] = v.z; As[kq + 3][r] = v.w;
        }
        // B: 16x64 of W1 and W3
        {
            int krow = tid >> 4, j4 = (tid & 15) << 2;
            *reinterpret_cast<float4*>(&B1s[krow][j4]) =
                *reinterpret_cast<const float4*>(W1e + (size_t)(k0 + krow) * HID + n0 + j4);
            *reinterpret_cast<float4*>(&B3s[krow][j4]) =
                *reinterpret_cast<const float4*>(W3e + (size_t)(k0 + krow) * HID + n0 + j4);
        }
        __syncthreads();
#pragma unroll
        for (int k = 0; k < 16; k++) {
            float4 a0 = *reinterpret_cast<float4*>(&As[k][ty * 8]);
            float4 a1 = *reinterpret_cast<float4*>(&As[k][ty * 8 + 4]);
            const ull* pb1 = reinterpret_cast<const ull*>(&B1s[k][tx * 4]);
            const ull* pb3 = reinterpret_cast<const ull*>(&B3s[k][tx * 4]);
            ull b1a = pb1[0], b1b = pb1[1];
            ull b3a = pb3[0], b3b = pb3[1];
            float a[8] = {a0.x, a0.y, a0.z, a0.w, a1.x, a1.y, a1.z, a1.w};
#pragma unroll
            for (int i = 0; i < 8; i++) {
                ull aa = pack2(a[i], a[i]);
                c1[i][0] = fma2(aa, b1a, c1[i][0]);
                c1[i][1] = fma2(aa, b1b, c1[i][1]);
                c3[i][0] = fma2(aa, b3a, c3[i][0]);
                c3[i][1] = fma2(aa, b3b, c3[i][1]);
            }
        }
        __syncthreads();
    }
#pragma unroll
    for (int i = 0; i < 8; i++) {
        int m = ty * 8 + i;
        if (m < rows) {
            float z1[4], z3[4];
            unpack2(c1[i][0], z1[0], z1[1]); unpack2(c1[i][1], z1[2], z1[3]);
            unpack2(c3[i][0], z3[0], z3[1]); unpack2(c3[i][1], z3[2], z3[3]);
            float* dst = g_H + (size_t)(row0 + m) * HID + n0 + tx * 4;
#pragma unroll
            for (int j = 0; j < 4; j++) {
                float z = z1[j];
                dst[j] = (z / (1.f + __expf(-z))) * z3[j];  // silu(z1)*z3
            }
        }
    }
}

// GEMM2: P[row, d] = H[row, :] @ W2[e],  tiles [128 x 128]
__global__ __launch_bounds__(256, 2)
void gemm2_kernel(const float* __restrict__ W2) {
    if ((int)blockIdx.x >= g_ntiles) return;
    int e    = g_tile_e[blockIdx.x];
    int row0 = g_tile_r0[blockIdx.x];
    int rows = g_tile_rows[blockIdx.x];
    int n0   = blockIdx.y * 128;
    const float* W2e = W2 + (size_t)e * HID * DIM;

    __shared__ __align__(16) float As[16][128];
    __shared__ __align__(16) float Bs[16][128];

    int tid = threadIdx.x;
    ull c[8][4];
#pragma unroll
    for (int i = 0; i < 8; i++)
#pragma unroll
        for (int j = 0; j < 4; j++) c[i][j] = 0ull;
    int ty = tid >> 4, tx = tid & 15;

    for (int k0 = 0; k0 < HID; k0 += 16) {
#pragma unroll
        for (int p = 0; p < 2; p++) {
            int idx = p * 256 + tid;
            int r = idx >> 2, kq = (idx & 3) << 2;
            float4 v = make_float4(0.f, 0.f, 0.f, 0.f);
            if (r < rows)
                v = *reinterpret_cast<const float4*>(g_H + (size_t)(row0 + r) * HID + k0 + kq);
            As[kq + 0][r] = v.x; As[kq + 1][r] = v.y;
            As[kq + 2][r] = v.z; As[kq + 3][r] = v.w;
        }
#pragma unroll
        for (int p = 0; p < 2; p++) {
            int idx = p * 256 + tid;
            int krow = idx >> 5, j4 = (idx & 31) << 2;
            *reinterpret_cast<float4*>(&Bs[krow][j4]) =
                *reinterpret_cast<const float4*>(W2e + (size_t)(k0 + krow) * DIM + n0 + j4);
        }
        __syncthreads();
#pragma unroll
        for (int k = 0; k < 16; k++) {
            float4 a0 = *reinterpret_cast<float4*>(&As[k][ty * 8]);
            float4 a1 = *reinterpret_cast<float4*>(&As[k][ty * 8 + 4]);
            const ull* pb = reinterpret_cast<const ull*>(&Bs[k][tx * 8]);
            ull b0 = pb[0], b1 = pb[1], b2 = pb[2], b3 = pb[3];
            float a[8] = {a0.x, a0.y, a0.z, a0.w, a1.x, a1.y, a1.z, a1.w};
#pragma unroll
            for (int i = 0; i < 8; i++) {
                ull aa = pack2(a[i], a[i]);
                c[i][0] = fma2(aa, b0, c[i][0]);
                c[i][1] = fma2(aa, b1, c[i][1]);
                c[i][2] = fma2(aa, b2, c[i][2]);
                c[i][3] = fma2(aa, b3, c[i][3]);
            }
        }
        __syncthreads();
    }
#pragma unroll
    for (int i = 0; i < 8; i++) {
        int m = ty * 8 + i;
        if (m < rows) {
            float* dst = g_P + (size_t)(row0 + m) * DIM + n0 + tx * 8;
#pragma unroll
            for (int j = 0; j < 4; j++) {
                float f0, f1;
                unpack2(c[i][j], f0, f1);
                dst[j * 2 + 0] = f0;
                dst[j * 2 + 1] = f1;
            }
        }
    }
}

// combine: out[t] = g0 * P[pos(t,0)] + g1 * P[pos(t,1)]
__global__ void combine_kernel(float* __restrict__ out) {
    int t = blockIdx.x;
    int d = threadIdx.x * 4;
    int pb = t * 2;
    int r0 = g_pos[pb], r1 = g_pos[pb + 1];
    float g0 = g_gate[pb], g1 = g_gate[pb + 1];
    float4 v0 = *reinterpret_cast<const float4*>(g_P + (size_t)r0 * DIM + d);
    float4 v1 = *reinterpret_cast<const float4*>(g_P + (size_t)r1 * DIM + d);
    float4 o;
    o.x = g0 * v0.x + g1 * v1.x;
    o.y = g0 * v0.y + g1 * v1.y;
    o.z = g0 * v0.z + g1 * v1.z;
    o.w = g0 * v0.w + g1 * v1.w;
    *reinterpret_cast<float4*>(out + (size_t)t * DIM + d) = o;
}

// ---------------- launch -----------------------------------------------------
extern "C" void kernel_launch(void* const* d_in, const int* in_sizes, int n_in,
                              void* d_out, int out_size) {
    (void)in_sizes; (void)n_in; (void)out_size;
    const float* x  = (const float*)d_in[0];
    const float* Wr = (const float*)d_in[1];
    const float* W1 = (const float*)d_in[2];
    const float* W2 = (const float*)d_in[3];
    const float* W3 = (const float*)d_in[4];
    float* out = (float*)d_out;

    init_kernel<<<1, 32>>>();
    router_kernel<<<T_TOK / 8, 256>>>(x, Wr);
    scan_kernel<<<1, 1>>>();
    scatter_kernel<<<NP / 256, 256>>>();
    gemm1_kernel<<<dim3(MAXTILES, HID / 64), 256>>>(x, W1, W3);
    gemm2_kernel<<<dim3(MAXTILES, DIM / 128), 256>>>(W2);
    combine_kernel<<<T_TOK, 256>>>(out);
}

// round 6
// speedup vs baseline: 1.1511x; 1.1511x over previous
#include <cuda_runtime.h>
#include <cuda_bf16.h>
#include <mma.h>
#include <cstdint>

using namespace nvcuda;
typedef unsigned long long ull;

#define T_TOK 4096
#define DIM   1024
#define HID   2048
#define NEXP  8
#define NP    (T_TOK * 2)
#define BM    128
#define MAXTILES (NP / BM + NEXP)   // 72

// ---------------- scratch (same set as the R1 PASSING kernel) ---------------
__device__ int   g_pair[NP];
__device__ int   g_pos[NP];
__device__ float g_gate[NP];
__device__ int   g_expert[NP];
__device__ int   g_counts[NEXP];
__device__ int   g_fill[NEXP];
__device__ int   g_offs[NEXP + 1];
__device__ int   g_tile_e[MAXTILES];
__device__ int   g_tile_r0[MAXTILES];
__device__ int   g_tile_rows[MAXTILES];
__device__ int   g_ntiles;
__device__ float g_H[(size_t)NP * HID];   // 64 MB fp32 hidden
__device__ float g_P[(size_t)NP * DIM];   // 32 MB fp32 per-pair outputs

// ---------------- helpers ----------------------------------------------------
__device__ __forceinline__ void split_bf(float v, uint16_t& h, uint16_t& l) {
    __nv_bfloat16 bh = __float2bfloat16_rn(v);
    float fh = __bfloat162float(bh);
    __nv_bfloat16 bl = __float2bfloat16_rn(v - fh);
    h = __bfloat16_as_ushort(bh);
    l = __bfloat16_as_ushort(bl);
}
__device__ __forceinline__ void split4(float4 v, ull& hp, ull& lp) {
    uint16_t h0, h1, h2, h3, l0, l1, l2, l3;
    split_bf(v.x, h0, l0); split_bf(v.y, h1, l1);
    split_bf(v.z, h2, l2); split_bf(v.w, h3, l3);
    hp = (ull)h0 | ((ull)h1 << 16) | ((ull)h2 << 32) | ((ull)h3 << 48);
    lp = (ull)l0 | ((ull)l1 << 16) | ((ull)l2 << 32) | ((ull)l3 << 48);
}

// ---------------- routing path (verbatim from the R1 passing kernel) ---------
__global__ void init_kernel() {
    int t = threadIdx.x;
    if (t < NEXP) { g_counts[t] = 0; g_fill[t] = 0; }
}

__global__ void router_kernel(const float* __restrict__ x,
                              const float* __restrict__ Wr) {
    int warp = (blockIdx.x * blockDim.x + threadIdx.x) >> 5;
    int lane = threadIdx.x & 31;
    if (warp >= T_TOK) return;
    const float* xr = x + (size_t)warp * DIM;
    float acc[NEXP];
#pragma unroll
    for (int e = 0; e < NEXP; e++) acc[e] = 0.f;
    for (int d = lane; d < DIM; d += 32) {
        float xv = xr[d];
        const float4* w = reinterpret_cast<const float4*>(Wr + (size_t)d * NEXP);
        float4 w0 = w[0], w1 = w[1];
        acc[0] = fmaf(xv, w0.x, acc[0]); acc[1] = fmaf(xv, w0.y, acc[1]);
        acc[2] = fmaf(xv, w0.z, acc[2]); acc[3] = fmaf(xv, w0.w, acc[3]);
        acc[4] = fmaf(xv, w1.x, acc[4]); acc[5] = fmaf(xv, w1.y, acc[5]);
        acc[6] = fmaf(xv, w1.z, acc[6]); acc[7] = fmaf(xv, w1.w, acc[7]);
    }
#pragma unroll
    for (int off = 16; off > 0; off >>= 1)
#pragma unroll
        for (int e = 0; e < NEXP; e++)
            acc[e] += __shfl_down_sync(0xffffffffu, acc[e], off);
    if (lane == 0) {
        int i0 = 0; float m0 = acc[0];
#pragma unroll
        for (int e = 1; e < NEXP; e++)
            if (acc[e] > m0) { m0 = acc[e]; i0 = e; }
        int i1 = -1; float m1 = -3.4e38f;
#pragma unroll
        for (int e = 0; e < NEXP; e++)
            if (e != i0 && acc[e] > m1) { m1 = acc[e]; i1 = e; }
        float g0 = 1.f / (1.f + expf(m1 - m0));
        int p0 = warp * 2, p1 = p0 + 1;
        g_expert[p0] = i0; g_gate[p0] = g0;
        g_expert[p1] = i1; g_gate[p1] = 1.f - g0;
        atomicAdd(&g_counts[i0], 1);
        atomicAdd(&g_counts[i1], 1);
    }
}

__global__ void scan_kernel() {
    int off = 0;
    for (int e = 0; e < NEXP; e++) { g_offs[e] = off; off += g_counts[e]; }
    g_offs[NEXP] = off;
    int nt = 0;
    for (int e = 0; e < NEXP; e++) {
        int c = g_counts[e], base = g_offs[e];
        for (int r = 0; r < c; r += BM) {
            g_tile_e[nt] = e; g_tile_r0[nt] = base + r;
            g_tile_rows[nt] = (c - r < BM) ? (c - r) : BM;
            nt++;
        }
    }
    g_ntiles = nt;
}

__global__ void scatter_kernel() {
    int p = blockIdx.x * blockDim.x + threadIdx.x;
    if (p >= NP) return;
    int e = g_expert[p];
    int row = g_offs[e] + atomicAdd(&g_fill[e], 1);
    g_pair[row] = p;
    g_pos[p] = row;
}

// ---------------- GEMM1 (WMMA, on-the-fly split): h = silu(x@W1)*(x@W3) -----
// smem elements (bf16): Ah[128*40] @0 | Al @5120 | B1h[32*72] @10240 |
//   B1l @12544 | B3h @14848 | B3l @17152   (total 19456 elem = 38912 B)
// stage (fp32, reuse): [128][72] = 36864 B
#define G1_SMEM 38912

__global__ __launch_bounds__(256)
void gemm1_wmma(const float* __restrict__ x,
                const float* __restrict__ W1,
                const float* __restrict__ W3) {
    if ((int)blockIdx.x >= g_ntiles) return;
    __shared__ __align__(16) char sm[G1_SMEM];
    __shared__ int s_tok[128];
    __nv_bfloat16* Ah  = (__nv_bfloat16*)sm;
    __nv_bfloat16* Al  = Ah + 5120;
    __nv_bfloat16* B1h = Ah + 10240;
    __nv_bfloat16* B1l = Ah + 12544;
    __nv_bfloat16* B3h = Ah + 14848;
    __nv_bfloat16* B3l = Ah + 17152;
    float* stage = (float*)sm;                 // ld 72, reused after mainloop

    int e    = g_tile_e[blockIdx.x];
    int row0 = g_tile_r0[blockIdx.x];
    int rows = g_tile_rows[blockIdx.x];
    int n0   = blockIdx.y * 64;
    int tid  = threadIdx.x, wid = tid >> 5;
    int wm = wid & 3, wn = wid >> 2;

    if (tid < 128) s_tok[tid] = (tid < rows) ? (g_pair[row0 + tid] >> 1) : -1;
    __syncthreads();

    const float* W1e = W1 + (size_t)e * DIM * HID;   // [K=DIM][N=HID]
    const float* W3e = W3 + (size_t)e * DIM * HID;

    wmma::fragment<wmma::accumulator, 16, 16, 16, float> acc1[2][2], acc3[2][2];
#pragma unroll
    for (int i = 0; i < 2; i++)
#pragma unroll
        for (int j = 0; j < 2; j++) {
            wmma::fill_fragment(acc1[i][j], 0.f);
            wmma::fill_fragment(acc3[i][j], 0.f);
        }

    for (int ch = 0; ch < DIM / 32; ch++) {
        int k0 = ch * 32;
        // A fill: gather fp32 rows of x, split -> Ah/Al. 128 rows x 8 float4.
#pragma unroll
        for (int p = 0; p < 4; p++) {
            int li = p * 256 + tid;
            int r = li >> 3, q = li & 7;
            int tok = s_tok[r];
            float4 v = make_float4(0.f, 0.f, 0.f, 0.f);
            if (tok >= 0)
                v = *reinterpret_cast<const float4*>(x + (size_t)tok * DIM + k0 + q * 4);
            ull hp, lp; split4(v, hp, lp);
            *reinterpret_cast<ull*>(Ah + r * 40 + q * 4) = hp;
            *reinterpret_cast<ull*>(Al + r * 40 + q * 4) = lp;
        }
        // B fill: W1 and W3 fp32 [32 k-rows][64 n-cols], split. 2 x 512 float4.
#pragma unroll
        for (int p = 0; p < 4; p++) {
            int li = p * 256 + tid;
            int t = li >> 9, rr = li & 511, r = rr >> 4, q = rr & 15;
            const float* src = t ? W3e : W1e;
            float4 v = *reinterpret_cast<const float4*>(
                src + (size_t)(k0 + r) * HID + n0 + q * 4);
            ull hp, lp; split4(v, hp, lp);
            __nv_bfloat16* dh = t ? B3h : B1h;
            __nv_bfloat16* dl = t ? B3l : B1l;
            *reinterpret_cast<ull*>(dh + r * 72 + q * 4) = hp;
            *reinterpret_cast<ull*>(dl + r * 72 + q * 4) = lp;
        }
        __syncthreads();

#pragma unroll
        for (int ks = 0; ks < 2; ks++) {
            wmma::fragment<wmma::matrix_a, 16, 16, 16, __nv_bfloat16, wmma::row_major> ah[2], al[2];
#pragma unroll
            for (int i = 0; i < 2; i++) {
                wmma::load_matrix_sync(ah[i], Ah + (wm * 32 + i * 16) * 40 + ks * 16, 40);
                wmma::load_matrix_sync(al[i], Al + (wm * 32 + i * 16) * 40 + ks * 16, 40);
            }
            int bcol = wn * 32;
#pragma unroll
            for (int j = 0; j < 2; j++) {
                wmma::fragment<wmma::matrix_b, 16, 16, 16, __nv_bfloat16, wmma::row_major> bh, bl;
                wmma::load_matrix_sync(bh, B1h + ks * 16 * 72 + bcol + j * 16, 72);
                wmma::load_matrix_sync(bl, B1l + ks * 16 * 72 + bcol + j * 16, 72);
#pragma unroll
                for (int i = 0; i < 2; i++) {
                    wmma::mma_sync(acc1[i][j], ah[i], bh, acc1[i][j]);
                    wmma::mma_sync(acc1[i][j], al[i], bh, acc1[i][j]);
                    wmma::mma_sync(acc1[i][j], ah[i], bl, acc1[i][j]);
                }
                wmma::load_matrix_sync(bh, B3h + ks * 16 * 72 + bcol + j * 16, 72);
                wmma::load_matrix_sync(bl, B3l + ks * 16 * 72 + bcol + j * 16, 72);
#pragma unroll
                for (int i = 0; i < 2; i++) {
                    wmma::mma_sync(acc3[i][j], ah[i], bh, acc3[i][j]);
                    wmma::mma_sync(acc3[i][j], al[i], bh, acc3[i][j]);
                    wmma::mma_sync(acc3[i][j], ah[i], bl, acc3[i][j]);
                }
            }
        }
        __syncthreads();
    }

    // epilogue: silu(z1)*z3 in-fragment, stage to smem, fp32 write to g_H
#pragma unroll
    for (int i = 0; i < 2; i++)
#pragma unroll
        for (int j = 0; j < 2; j++) {
#pragma unroll
            for (int t = 0; t < acc1[i][j].num_elements; t++) {
                float z = acc1[i][j].x[t];
                acc1[i][j].x[t] = z / (1.f + __expf(-z)) * acc3[i][j].x[t];
            }
            wmma::store_matrix_sync(stage + (wm * 32 + i * 16) * 72 + wn * 32 + j * 16,
                                    acc1[i][j], 72, wmma::mem_row_major);
        }
    __syncthreads();

    int row = tid >> 1, half = tid & 1;
    if (row < rows) {
        float* dst = g_H + (size_t)(row0 + row) * HID + n0 + half * 32;
#pragma unroll
        for (int j = 0; j < 8; j++)
            *reinterpret_cast<float4*>(dst + j * 4) =
                *reinterpret_cast<const float4*>(stage + row * 72 + half * 32 + j * 4);
    }
}

// ---------------- GEMM2 (WMMA, on-the-fly split): P = h @ W2 ----------------
// smem elements (bf16): Ah[128*40] @0 | Al @5120 | Bh[32*72] @10240 | Bl @12544
//   (14848 elem = 29696 B); stage fp32 36864 B -> buffer 36864
#define G2_SMEM 36864

__global__ __launch_bounds__(256)
void gemm2_wmma(const float* __restrict__ W2) {
    if ((int)blockIdx.x >= g_ntiles) return;
    __shared__ __align__(16) char sm[G2_SMEM];
    __nv_bfloat16* Ah = (__nv_bfloat16*)sm;
    __nv_bfloat16* Al = Ah + 5120;
    __nv_bfloat16* Bh = Ah + 10240;
    __nv_bfloat16* Bl = Ah + 12544;
    float* stage = (float*)sm;

    int e    = g_tile_e[blockIdx.x];
    int row0 = g_tile_r0[blockIdx.x];
    int rows = g_tile_rows[blockIdx.x];
    int n0   = blockIdx.y * 64;
    int tid  = threadIdx.x, wid = tid >> 5;
    int wm = wid & 3, wn = wid >> 2;

    const float* W2e = W2 + (size_t)e * HID * DIM;   // [K=HID][N=DIM]

    wmma::fragment<wmma::accumulator, 16, 16, 16, float> acc[2][2];
#pragma unroll
    for (int i = 0; i < 2; i++)
#pragma unroll
        for (int j = 0; j < 2; j++) wmma::fill_fragment(acc[i][j], 0.f);

    for (int ch = 0; ch < HID / 32; ch++) {
        int k0 = ch * 32;
        // A fill from g_H fp32 (guarded), split
#pragma unroll
        for (int p = 0; p < 4; p++) {
            int li = p * 256 + tid;
            int r = li >> 3, q = li & 7;
            float4 v = make_float4(0.f, 0.f, 0.f, 0.f);
            if (r < rows)
                v = *reinterpret_cast<const float4*>(
                    g_H + (size_t)(row0 + r) * HID + k0 + q * 4);
            ull hp, lp; split4(v, hp, lp);
            *reinterpret_cast<ull*>(Ah + r * 40 + q * 4) = hp;
            *reinterpret_cast<ull*>(Al + r * 40 + q * 4) = lp;
        }
        // B fill: W2 fp32 [32][64], split. 512 float4.
#pragma unroll
        for (int p = 0; p < 2; p++) {
            int li = p * 256 + tid;
            int r = li >> 4, q = li & 15;
            float4 v = *reinterpret_cast<const float4*>(
                W2e + (size_t)(k0 + r) * DIM + n0 + q * 4);
            ull hp, lp; split4(v, hp, lp);
            *reinterpret_cast<ull*>(Bh + r * 72 + q * 4) = hp;
            *reinterpret_cast<ull*>(Bl + r * 72 + q * 4) = lp;
        }
        __syncthreads();

#pragma unroll
        for (int ks = 0; ks < 2; ks++) {
            wmma::fragment<wmma::matrix_a, 16, 16, 16, __nv_bfloat16, wmma::row_major> ah[2], al[2];
#pragma unroll
            for (int i = 0; i < 2; i++) {
                wmma::load_matrix_sync(ah[i], Ah + (wm * 32 + i * 16) * 40 + ks * 16, 40);
                wmma::load_matrix_sync(al[i], Al + (wm * 32 + i * 16) * 40 + ks * 16, 40);
            }
#pragma unroll
            for (int j = 0; j < 2; j++) {
                wmma::fragment<wmma::matrix_b, 16, 16, 16, __nv_bfloat16, wmma::row_major> bh, bl;
                int bcol = wn * 32 + j * 16;
                wmma::load_matrix_sync(bh, Bh + ks * 16 * 72 + bcol, 72);
                wmma::load_matrix_sync(bl, Bl + ks * 16 * 72 + bcol, 72);
#pragma unroll
                for (int i = 0; i < 2; i++) {
                    wmma::mma_sync(acc[i][j], ah[i], bh, acc[i][j]);
                    wmma::mma_sync(acc[i][j], al[i], bh, acc[i][j]);
                    wmma::mma_sync(acc[i][j], ah[i], bl, acc[i][j]);
                }
            }
        }
        __syncthreads();
    }

#pragma unroll
    for (int i = 0; i < 2; i++)
#pragma unroll
        for (int j = 0; j < 2; j++)
            wmma::store_matrix_sync(stage + (wm * 32 + i * 16) * 72 + wn * 32 + j * 16,
                                    acc[i][j], 72, wmma::mem_row_major);
    __syncthreads();

    int row = tid >> 1, half = tid & 1;
    if (row < rows) {
        float* dst = g_P + (size_t)(row0 + row) * DIM + n0 + half * 32;
#pragma unroll
        for (int j = 0; j < 8; j++)
            *reinterpret_cast<float4*>(dst + j * 4) =
                *reinterpret_cast<const float4*>(stage + row * 72 + half * 32 + j * 4);
    }
}

// ---------------- combine (verbatim R1) --------------------------------------
__global__ void combine_kernel(float* __restrict__ out) {
    int t = blockIdx.x;
    int d = threadIdx.x * 4;
    int pb = t * 2;
    int r0 = g_pos[pb], r1 = g_pos[pb + 1];
    float g0 = g_gate[pb], g1 = g_gate[pb + 1];
    float4 v0 = *reinterpret_cast<const float4*>(g_P + (size_t)r0 * DIM + d);
    float4 v1 = *reinterpret_cast<const float4*>(g_P + (size_t)r1 * DIM + d);
    float4 o;
    o.x = g0 * v0.x + g1 * v1.x;
    o.y = g0 * v0.y + g1 * v1.y;
    o.z = g0 * v0.z + g1 * v1.z;
    o.w = g0 * v0.w + g1 * v1.w;
    *reinterpret_cast<float4*>(out + (size_t)t * DIM + d) = o;
}

// ---------------- launch (same 7-launch sequence as R1) ----------------------
extern "C" void kernel_launch(void* const* d_in, const int* in_sizes, int n_in,
                              void* d_out, int out_size) {
    (void)in_sizes; (void)n_in; (void)out_size;
    const float* x  = (const float*)d_in[0];
    const float* Wr = (const float*)d_in[1];
    const float* W1 = (const float*)d_in[2];
    const float* W2 = (const float*)d_in[3];
    const float* W3 = (const float*)d_in[4];
    float* out = (float*)d_out;

    init_kernel<<<1, 32>>>();
    router_kernel<<<T_TOK / 8, 256>>>(x, Wr);
    scan_kernel<<<1, 1>>>();
    scatter_kernel<<<NP / 256, 256>>>();
    gemm1_wmma<<<dim3(MAXTILES, HID / 64), 256>>>(x, W1, W3);
    gemm2_wmma<<<dim3(MAXTILES, DIM / 64), 256>>>(W2);
    combine_kernel<<<T_TOK, 256>>>(out);
}

// round 7
// speedup vs baseline: 1.3102x; 1.1382x over previous
#include <cuda_runtime.h>
#include <cuda_bf16.h>
#include <mma.h>
#include <cstdint>

using namespace nvcuda;
typedef unsigned long long ull;

#define T_TOK 4096
#define DIM   1024
#define HID   2048
#define NEXP  8
#define NP    (T_TOK * 2)
#define BM    128
#define MAXTILES (NP / BM + NEXP)   // 72

// ---------------- scratch (<=100 MB total; no prep kernels) ------------------
__device__ int   g_pair[NP];
__device__ int   g_pos[NP];
__device__ float g_gate[NP];
__device__ int   g_expert[NP];
__device__ int   g_counts[NEXP];
__device__ int   g_fill[NEXP];
__device__ int   g_offs[NEXP + 1];
__device__ int   g_tile_e[MAXTILES];
__device__ int   g_tile_r0[MAXTILES];
__device__ int   g_tile_rows[MAXTILES];
__device__ int   g_ntiles;
__device__ float g_P[(size_t)NP * DIM];               // 32 MB
__device__ __nv_bfloat16 g_Hh[(size_t)NP * HID];      // 32 MB (hidden, hi)
__device__ __nv_bfloat16 g_Hl[(size_t)NP * HID];      // 32 MB (hidden, lo)

// ---------------- helpers ----------------------------------------------------
__device__ __forceinline__ void split_bf(float v, uint16_t& h, uint16_t& l) {
    __nv_bfloat16 bh = __float2bfloat16_rn(v);
    float fh = __bfloat162float(bh);
    __nv_bfloat16 bl = __float2bfloat16_rn(v - fh);
    h = __bfloat16_as_ushort(bh);
    l = __bfloat16_as_ushort(bl);
}
__device__ __forceinline__ void split4(float4 v, ull& hp, ull& lp) {
    uint16_t h0, h1, h2, h3, l0, l1, l2, l3;
    split_bf(v.x, h0, l0); split_bf(v.y, h1, l1);
    split_bf(v.z, h2, l2); split_bf(v.w, h3, l3);
    hp = (ull)h0 | ((ull)h1 << 16) | ((ull)h2 << 32) | ((ull)h3 << 48);
    lp = (ull)l0 | ((ull)l1 << 16) | ((ull)l2 << 32) | ((ull)l3 << 48);
}

// ---------------- routing path (verbatim, proven) -----------------------------
__global__ void init_kernel() {
    int t = threadIdx.x;
    if (t < NEXP) { g_counts[t] = 0; g_fill[t] = 0; }
}

__global__ void router_kernel(const float* __restrict__ x,
                              const float* __restrict__ Wr) {
    int warp = (blockIdx.x * blockDim.x + threadIdx.x) >> 5;
    int lane = threadIdx.x & 31;
    if (warp >= T_TOK) return;
    const float* xr = x + (size_t)warp * DIM;
    float acc[NEXP];
#pragma unroll
    for (int e = 0; e < NEXP; e++) acc[e] = 0.f;
    for (int d = lane; d < DIM; d += 32) {
        float xv = xr[d];
        const float4* w = reinterpret_cast<const float4*>(Wr + (size_t)d * NEXP);
        float4 w0 = w[0], w1 = w[1];
        acc[0] = fmaf(xv, w0.x, acc[0]); acc[1] = fmaf(xv, w0.y, acc[1]);
        acc[2] = fmaf(xv, w0.z, acc[2]); acc[3] = fmaf(xv, w0.w, acc[3]);
        acc[4] = fmaf(xv, w1.x, acc[4]); acc[5] = fmaf(xv, w1.y, acc[5]);
        acc[6] = fmaf(xv, w1.z, acc[6]); acc[7] = fmaf(xv, w1.w, acc[7]);
    }
#pragma unroll
    for (int off = 16; off > 0; off >>= 1)
#pragma unroll
        for (int e = 0; e < NEXP; e++)
            acc[e] += __shfl_down_sync(0xffffffffu, acc[e], off);
    if (lane == 0) {
        int i0 = 0; float m0 = acc[0];
#pragma unroll
        for (int e = 1; e < NEXP; e++)
            if (acc[e] > m0) { m0 = acc[e]; i0 = e; }
        int i1 = -1; float m1 = -3.4e38f;
#pragma unroll
        for (int e = 0; e < NEXP; e++)
            if (e != i0 && acc[e] > m1) { m1 = acc[e]; i1 = e; }
        float g0 = 1.f / (1.f + expf(m1 - m0));
        int p0 = warp * 2, p1 = p0 + 1;
        g_expert[p0] = i0; g_gate[p0] = g0;
        g_expert[p1] = i1; g_gate[p1] = 1.f - g0;
        atomicAdd(&g_counts[i0], 1);
        atomicAdd(&g_counts[i1], 1);
    }
}

__global__ void scan_kernel() {
    int off = 0;
    for (int e = 0; e < NEXP; e++) { g_offs[e] = off; off += g_counts[e]; }
    g_offs[NEXP] = off;
    int nt = 0;
    for (int e = 0; e < NEXP; e++) {
        int c = g_counts[e], base = g_offs[e];
        for (int r = 0; r < c; r += BM) {
            g_tile_e[nt] = e; g_tile_r0[nt] = base + r;
            g_tile_rows[nt] = (c - r < BM) ? (c - r) : BM;
            nt++;
        }
    }
    g_ntiles = nt;
}

__global__ void scatter_kernel() {
    int p = blockIdx.x * blockDim.x + threadIdx.x;
    if (p >= NP) return;
    int e = g_expert[p];
    int row = g_offs[e] + atomicAdd(&g_fill[e], 1);
    g_pair[row] = p;
    g_pos[p] = row;
}

// ---------------- GEMM1: h = silu(x@W1)*(x@W3), pipelined bf16x3 -------------
// smem (bf16 elems): Ah[128*40]@0 | Al@5120 | B1h[32*72]@10240 | B1l@12544 |
//   B3h@14848 | B3l@17152  -> 19456 elem = 38912 B; fp32 stage reuses (36864 B)
#define G1_SMEM 38912

__global__ __launch_bounds__(256)
void gemm1_wmma(const float* __restrict__ x,
                const float* __restrict__ W1,
                const float* __restrict__ W3) {
    if ((int)blockIdx.x >= g_ntiles) return;
    __shared__ __align__(16) char sm[G1_SMEM];
    __shared__ int s_tok[128];
    __nv_bfloat16* Ah  = (__nv_bfloat16*)sm;
    __nv_bfloat16* Al  = Ah + 5120;
    __nv_bfloat16* B1h = Ah + 10240;
    __nv_bfloat16* B1l = Ah + 12544;
    __nv_bfloat16* B3h = Ah + 14848;
    __nv_bfloat16* B3l = Ah + 17152;
    float* stage = (float*)sm;

    int e    = g_tile_e[blockIdx.x];
    int row0 = g_tile_r0[blockIdx.x];
    int rows = g_tile_rows[blockIdx.x];
    int n0   = blockIdx.y * 64;
    int tid  = threadIdx.x, wid = tid >> 5;
    int wm = wid & 3, wn = wid >> 2;

    if (tid < 128) s_tok[tid] = (tid < rows) ? (g_pair[row0 + tid] >> 1) : -1;
    __syncthreads();

    const float* W1e = W1 + (size_t)e * DIM * HID;   // [K=DIM][N=HID]
    const float* W3e = W3 + (size_t)e * DIM * HID;

    // per-thread load coords (fixed across chunks)
    int ar[4], aq[4], atok[4];
#pragma unroll
    for (int p = 0; p < 4; p++) {
        int li = p * 256 + tid;
        ar[p] = li >> 3; aq[p] = li & 7;
        atok[p] = s_tok[ar[p]];
    }
    int bt[4], br[4], bq[4];
#pragma unroll
    for (int p = 0; p < 4; p++) {
        int li = p * 256 + tid;
        bt[p] = li >> 9; int rr = li & 511;
        br[p] = rr >> 4; bq[p] = rr & 15;
    }

    wmma::fragment<wmma::accumulator, 16, 16, 16, float> acc1[2][2], acc3[2][2];
#pragma unroll
    for (int i = 0; i < 2; i++)
#pragma unroll
        for (int j = 0; j < 2; j++) {
            wmma::fill_fragment(acc1[i][j], 0.f);
            wmma::fill_fragment(acc3[i][j], 0.f);
        }

    float4 va[4], vb[4];
    // prefetch chunk 0
#pragma unroll
    for (int p = 0; p < 4; p++)
        va[p] = (atok[p] >= 0)
              ? *reinterpret_cast<const float4*>(x + (size_t)atok[p] * DIM + aq[p] * 4)
              : make_float4(0.f, 0.f, 0.f, 0.f);
#pragma unroll
    for (int p = 0; p < 4; p++) {
        const float* src = bt[p] ? W3e : W1e;
        vb[p] = *reinterpret_cast<const float4*>(src + (size_t)br[p] * HID + n0 + bq[p] * 4);
    }

    for (int ch = 0; ch < DIM / 32; ch++) {
        // split + store the prefetched chunk
#pragma unroll
        for (int p = 0; p < 4; p++) {
            ull hp, lp; split4(va[p], hp, lp);
            *reinterpret_cast<ull*>(Ah + ar[p] * 40 + aq[p] * 4) = hp;
            *reinterpret_cast<ull*>(Al + ar[p] * 40 + aq[p] * 4) = lp;
        }
#pragma unroll
        for (int p = 0; p < 4; p++) {
            ull hp, lp; split4(vb[p], hp, lp);
            __nv_bfloat16* dh = bt[p] ? B3h : B1h;
            __nv_bfloat16* dl = bt[p] ? B3l : B1l;
            *reinterpret_cast<ull*>(dh + br[p] * 72 + bq[p] * 4) = hp;
            *reinterpret_cast<ull*>(dl + br[p] * 72 + bq[p] * 4) = lp;
        }
        __syncthreads();

        // issue next chunk's LDGs (latency hidden under MMA)
        if (ch + 1 < DIM / 32) {
            int k0n = (ch + 1) * 32;
#pragma unroll
            for (int p = 0; p < 4; p++)
                va[p] = (atok[p] >= 0)
                      ? *reinterpret_cast<const float4*>(x + (size_t)atok[p] * DIM + k0n + aq[p] * 4)
                      : make_float4(0.f, 0.f, 0.f, 0.f);
#pragma unroll
            for (int p = 0; p < 4; p++) {
                const float* src = bt[p] ? W3e : W1e;
                vb[p] = *reinterpret_cast<const float4*>(
                    src + (size_t)(k0n + br[p]) * HID + n0 + bq[p] * 4);
            }
        }

        // MMA: two a-phases to limit register lifetime
#pragma unroll
        for (int ks = 0; ks < 2; ks++) {
            wmma::fragment<wmma::matrix_a, 16, 16, 16, __nv_bfloat16, wmma::row_major> af[2];
            // phase 1: a = hi
#pragma unroll
            for (int i = 0; i < 2; i++)
                wmma::load_matrix_sync(af[i], Ah + (wm * 32 + i * 16) * 40 + ks * 16, 40);
#pragma unroll
            for (int j = 0; j < 2; j++) {
                int bcol = wn * 32 + j * 16;
                wmma::fragment<wmma::matrix_b, 16, 16, 16, __nv_bfloat16, wmma::row_major> bf;
                wmma::load_matrix_sync(bf, B1h + ks * 16 * 72 + bcol, 72);
#pragma unroll
                for (int i = 0; i < 2; i++) wmma::mma_sync(acc1[i][j], af[i], bf, acc1[i][j]);
                wmma::load_matrix_sync(bf, B1l + ks * 16 * 72 + bcol, 72);
#pragma unroll
                for (int i = 0; i < 2; i++) wmma::mma_sync(acc1[i][j], af[i], bf, acc1[i][j]);
                wmma::load_matrix_sync(bf, B3h + ks * 16 * 72 + bcol, 72);
#pragma unroll
                for (int i = 0; i < 2; i++) wmma::mma_sync(acc3[i][j], af[i], bf, acc3[i][j]);
                wmma::load_matrix_sync(bf, B3l + ks * 16 * 72 + bcol, 72);
#pragma unroll
                for (int i = 0; i < 2; i++) wmma::mma_sync(acc3[i][j], af[i], bf, acc3[i][j]);
            }
            // phase 2: a = lo (b hi only)
#pragma unroll
            for (int i = 0; i < 2; i++)
                wmma::load_matrix_sync(af[i], Al + (wm * 32 + i * 16) * 40 + ks * 16, 40);
#pragma unroll
            for (int j = 0; j < 2; j++) {
                int bcol = wn * 32 + j * 16;
                wmma::fragment<wmma::matrix_b, 16, 16, 16, __nv_bfloat16, wmma::row_major> bf;
                wmma::load_matrix_sync(bf, B1h + ks * 16 * 72 + bcol, 72);
#pragma unroll
                for (int i = 0; i < 2; i++) wmma::mma_sync(acc1[i][j], af[i], bf, acc1[i][j]);
                wmma::load_matrix_sync(bf, B3h + ks * 16 * 72 + bcol, 72);
#pragma unroll
                for (int i = 0; i < 2; i++) wmma::mma_sync(acc3[i][j], af[i], bf, acc3[i][j]);
            }
        }
        __syncthreads();
    }

    // epilogue: silu(z1)*z3 in-fragment, stage fp32, write SPLIT bf16 h
#pragma unroll
    for (int i = 0; i < 2; i++)
#pragma unroll
        for (int j = 0; j < 2; j++) {
#pragma unroll
            for (int t = 0; t < acc1[i][j].num_elements; t++) {
                float z = acc1[i][j].x[t];
                acc1[i][j].x[t] = z / (1.f + __expf(-z)) * acc3[i][j].x[t];
            }
            wmma::store_matrix_sync(stage + (wm * 32 + i * 16) * 72 + wn * 32 + j * 16,
                                    acc1[i][j], 72, wmma::mem_row_major);
        }
    __syncthreads();

    int row = tid >> 1, half = tid & 1;
    if (row < rows) {
        size_t ob = (size_t)(row0 + row) * HID + n0 + half * 32;
#pragma unroll
        for (int j = 0; j < 8; j++) {
            float4 v = *reinterpret_cast<const float4*>(stage + row * 72 + half * 32 + j * 4);
            ull hp, lp; split4(v, hp, lp);
            *reinterpret_cast<ull*>(&g_Hh[ob + j * 4]) = hp;
            *reinterpret_cast<ull*>(&g_Hl[ob + j * 4]) = lp;
        }
    }
}

// ---------------- GEMM2: P = h @ W2, pipelined, pre-split A -----------------
// smem (bf16): Ah[128*40]@0 | Al@5120 | Bh[32*72]@10240 | Bl@12544
//   -> 14848 elem = 29696 B; fp32 stage 36864 B
#define G2_SMEM 36864

__global__ __launch_bounds__(256)
void gemm2_wmma(const float* __restrict__ W2) {
    if ((int)blockIdx.x >= g_ntiles) return;
    __shared__ __align__(16) char sm[G2_SMEM];
    __nv_bfloat16* Ah = (__nv_bfloat16*)sm;
    __nv_bfloat16* Al = Ah + 5120;
    __nv_bfloat16* Bh = Ah + 10240;
    __nv_bfloat16* Bl = Ah + 12544;
    float* stage = (float*)sm;

    int e    = g_tile_e[blockIdx.x];
    int row0 = g_tile_r0[blockIdx.x];
    int rows = g_tile_rows[blockIdx.x];
    int n0   = blockIdx.y * 64;
    int tid  = threadIdx.x, wid = tid >> 5;
    int wm = wid & 3, wn = wid >> 2;

    const float* W2e = W2 + (size_t)e * HID * DIM;   // [K=HID][N=DIM]

    // A coords: 512 uint4 per buffer (hi, lo), 2 each per thread
    int ar[2], aq[2];
#pragma unroll
    for (int p = 0; p < 2; p++) {
        int li = p * 256 + tid;
        ar[p] = li >> 2; aq[p] = li & 3;
    }
    // B coords: 512 float4, 2 per thread
    int br[2], bq[2];
#pragma unroll
    for (int p = 0; p < 2; p++) {
        int li = p * 256 + tid;
        br[p] = li >> 4; bq[p] = li & 15;
    }

    wmma::fragment<wmma::accumulator, 16, 16, 16, float> acc[2][2];
#pragma unroll
    for (int i = 0; i < 2; i++)
#pragma unroll
        for (int j = 0; j < 2; j++) wmma::fill_fragment(acc[i][j], 0.f);

    uint4 vah[2], val[2];
    float4 vb[2];
    // prefetch chunk 0
#pragma unroll
    for (int p = 0; p < 2; p++) {
        if (ar[p] < rows) {
            size_t s = (size_t)(row0 + ar[p]) * HID + aq[p] * 8;
            vah[p] = *reinterpret_cast<const uint4*>(&g_Hh[s]);
            val[p] = *reinterpret_cast<const uint4*>(&g_Hl[s]);
        } else {
            vah[p] = make_uint4(0u, 0u, 0u, 0u);
            val[p] = make_uint4(0u, 0u, 0u, 0u);
        }
        vb[p] = *reinterpret_cast<const float4*>(W2e + (size_t)br[p] * DIM + n0 + bq[p] * 4);
    }

    for (int ch = 0; ch < HID / 32; ch++) {
        // store prefetched chunk (A: straight copies; B: split)
#pragma unroll
        for (int p = 0; p < 2; p++) {
            *reinterpret_cast<uint4*>(Ah + ar[p] * 40 + aq[p] * 8) = vah[p];
            *reinterpret_cast<uint4*>(Al + ar[p] * 40 + aq[p] * 8) = val[p];
            ull hp, lp; split4(vb[p], hp, lp);
            *reinterpret_cast<ull*>(Bh + br[p] * 72 + bq[p] * 4) = hp;
            *reinterpret_cast<ull*>(Bl + br[p] * 72 + bq[p] * 4) = lp;
        }
        __syncthreads();

        if (ch + 1 < HID / 32) {
            int k0n = (ch + 1) * 32;
#pragma unroll
            for (int p = 0; p < 2; p++) {
                if (ar[p] < rows) {
                    size_t s = (size_t)(row0 + ar[p]) * HID + k0n + aq[p] * 8;
                    vah[p] = *reinterpret_cast<const uint4*>(&g_Hh[s]);
                    val[p] = *reinterpret_cast<const uint4*>(&g_Hl[s]);
                }
                vb[p] = *reinterpret_cast<const float4*>(
                    W2e + (size_t)(k0n + br[p]) * DIM + n0 + bq[p] * 4);
            }
        }

#pragma unroll
        for (int ks = 0; ks < 2; ks++) {
            wmma::fragment<wmma::matrix_a, 16, 16, 16, __nv_bfloat16, wmma::row_major> af[2];
#pragma unroll
            for (int i = 0; i < 2; i++)
                wmma::load_matrix_sync(af[i], Ah + (wm * 32 + i * 16) * 40 + ks * 16, 40);
#pragma unroll
            for (int j = 0; j < 2; j++) {
                int bcol = wn * 32 + j * 16;
                wmma::fragment<wmma::matrix_b, 16, 16, 16, __nv_bfloat16, wmma::row_major> bf;
                wmma::load_matrix_sync(bf, Bh + ks * 16 * 72 + bcol, 72);
#pragma unroll
                for (int i = 0; i < 2; i++) wmma::mma_sync(acc[i][j], af[i], bf, acc[i][j]);
                wmma::load_matrix_sync(bf, Bl + ks * 16 * 72 + bcol, 72);
#pragma unroll
                for (int i = 0; i < 2; i++) wmma::mma_sync(acc[i][j], af[i], bf, acc[i][j]);
            }
#pragma unroll
            for (int i = 0; i < 2; i++)
                wmma::load_matrix_sync(af[i], Al + (wm * 32 + i * 16) * 40 + ks * 16, 40);
#pragma unroll
            for (int j = 0; j < 2; j++) {
                int bcol = wn * 32 + j * 16;
                wmma::fragment<wmma::matrix_b, 16, 16, 16, __nv_bfloat16, wmma::row_major> bf;
                wmma::load_matrix_sync(bf, Bh + ks * 16 * 72 + bcol, 72);
#pragma unroll
                for (int i = 0; i < 2; i++) wmma::mma_sync(acc[i][j], af[i], bf, acc[i][j]);
            }
        }
        __syncthreads();
    }

#pragma unroll
    for (int i = 0; i < 2; i++)
#pragma unroll
        for (int j = 0; j < 2; j++)
            wmma::store_matrix_sync(stage + (wm * 32 + i * 16) * 72 + wn * 32 + j * 16,
                                    acc[i][j], 72, wmma::mem_row_major);
    __syncthreads();

    int row = tid >> 1, half = tid & 1;
    if (row < rows) {
        float* dst = g_P + (size_t)(row0 + row) * DIM + n0 + half * 32;
#pragma unroll
        for (int j = 0; j < 8; j++)
            *reinterpret_cast<float4*>(dst + j * 4) =
                *reinterpret_cast<const float4*>(stage + row * 72 + half * 32 + j * 4);
    }
}

// ---------------- combine (verbatim) ------------------------------------------
__global__ void combine_kernel(float* __restrict__ out) {
    int t = blockIdx.x;
    int d = threadIdx.x * 4;
    int pb = t * 2;
    int r0 = g_pos[pb], r1 = g_pos[pb + 1];
    float g0 = g_gate[pb], g1 = g_gate[pb + 1];
    float4 v0 = *reinterpret_cast<const float4*>(g_P + (size_t)r0 * DIM + d);
    float4 v1 = *reinterpret_cast<const float4*>(g_P + (size_t)r1 * DIM + d);
    float4 o;
    o.x = g0 * v0.x + g1 * v1.x;
    o.y = g0 * v0.y + g1 * v1.y;
    o.z = g0 * v0.z + g1 * v1.z;
    o.w = g0 * v0.w + g1 * v1.w;
    *reinterpret_cast<float4*>(out + (size_t)t * DIM + d) = o;
}

// ---------------- launch (same 7-launch sequence) -----------------------------
extern "C" void kernel_launch(void* const* d_in, const int* in_sizes, int n_in,
                              void* d_out, int out_size) {
    (void)in_sizes; (void)n_in; (void)out_size;
    const float* x  = (const float*)d_in[0];
    const float* Wr = (const float*)d_in[1];
    const float* W1 = (const float*)d_in[2];
    const float* W2 = (const float*)d_in[3];
    const float* W3 = (const float*)d_in[4];
    float* out = (float*)d_out;

    init_kernel<<<1, 32>>>();
    router_kernel<<<T_TOK / 8, 256>>>(x, Wr);
    scan_kernel<<<1, 1>>>();
    scatter_kernel<<<NP / 256, 256>>>();
    gemm1_wmma<<<dim3(MAXTILES, HID / 64), 256>>>(x, W1, W3);
    gemm2_wmma<<<dim3(MAXTILES, DIM / 64), 256>>>(W2);
    combine_kernel<<<T_TOK, 256>>>(out);
}

// round 8
// speedup vs baseline: 1.6103x; 1.2291x over previous
#include <cuda_runtime.h>
#include <cuda_bf16.h>
#include <mma.h>
#include <cstdint>

using namespace nvcuda;
typedef unsigned long long ull;

#define T_TOK 4096
#define DIM   1024
#define HID   2048
#define NEXP  8
#define NP    (T_TOK * 2)
#define BM    128
#define MAXTILES (NP / BM + NEXP)   // 72

// ---------------- scratch (<=100 MB total; no prep kernels) ------------------
__device__ int   g_pair[NP];
__device__ int   g_pos[NP];
__device__ float g_gate[NP];
__device__ int   g_expert[NP];
__device__ int   g_counts[NEXP];
__device__ int   g_fill[NEXP];
__device__ int   g_offs[NEXP + 1];
__device__ int   g_tile_e[MAXTILES];
__device__ int   g_tile_r0[MAXTILES];
__device__ int   g_tile_rows[MAXTILES];
__device__ int   g_ntiles;
__device__ float g_P[(size_t)NP * DIM];               // 32 MB
__device__ __nv_bfloat16 g_Hh[(size_t)NP * HID];      // 32 MB (hidden, hi)
__device__ __nv_bfloat16 g_Hl[(size_t)NP * HID];      // 32 MB (hidden, lo)

// ---------------- helpers ----------------------------------------------------
__device__ __forceinline__ void split_bf(float v, uint16_t& h, uint16_t& l) {
    __nv_bfloat16 bh = __float2bfloat16_rn(v);
    float fh = __bfloat162float(bh);
    __nv_bfloat16 bl = __float2bfloat16_rn(v - fh);
    h = __bfloat16_as_ushort(bh);
    l = __bfloat16_as_ushort(bl);
}
__device__ __forceinline__ void split4(float4 v, ull& hp, ull& lp) {
    uint16_t h0, h1, h2, h3, l0, l1, l2, l3;
    split_bf(v.x, h0, l0); split_bf(v.y, h1, l1);
    split_bf(v.z, h2, l2); split_bf(v.w, h3, l3);
    hp = (ull)h0 | ((ull)h1 << 16) | ((ull)h2 << 32) | ((ull)h3 << 48);
    lp = (ull)l0 | ((ull)l1 << 16) | ((ull)l2 << 32) | ((ull)l3 << 48);
}

// ---------------- routing path (verbatim, proven) -----------------------------
__global__ void init_kernel() {
    int t = threadIdx.x;
    if (t < NEXP) { g_counts[t] = 0; g_fill[t] = 0; }
}

__global__ void router_kernel(const float* __restrict__ x,
                              const float* __restrict__ Wr) {
    int warp = (blockIdx.x * blockDim.x + threadIdx.x) >> 5;
    int lane = threadIdx.x & 31;
    if (warp >= T_TOK) return;
    const float* xr = x + (size_t)warp * DIM;
    float acc[NEXP];
#pragma unroll
    for (int e = 0; e < NEXP; e++) acc[e] = 0.f;
    for (int d = lane; d < DIM; d += 32) {
        float xv = xr[d];
        const float4* w = reinterpret_cast<const float4*>(Wr + (size_t)d * NEXP);
        float4 w0 = w[0], w1 = w[1];
        acc[0] = fmaf(xv, w0.x, acc[0]); acc[1] = fmaf(xv, w0.y, acc[1]);
        acc[2] = fmaf(xv, w0.z, acc[2]); acc[3] = fmaf(xv, w0.w, acc[3]);
        acc[4] = fmaf(xv, w1.x, acc[4]); acc[5] = fmaf(xv, w1.y, acc[5]);
        acc[6] = fmaf(xv, w1.z, acc[6]); acc[7] = fmaf(xv, w1.w, acc[7]);
    }
#pragma unroll
    for (int off = 16; off > 0; off >>= 1)
#pragma unroll
        for (int e = 0; e < NEXP; e++)
            acc[e] += __shfl_down_sync(0xffffffffu, acc[e], off);
    if (lane == 0) {
        int i0 = 0; float m0 = acc[0];
#pragma unroll
        for (int e = 1; e < NEXP; e++)
            if (acc[e] > m0) { m0 = acc[e]; i0 = e; }
        int i1 = -1; float m1 = -3.4e38f;
#pragma unroll
        for (int e = 0; e < NEXP; e++)
            if (e != i0 && acc[e] > m1) { m1 = acc[e]; i1 = e; }
        float g0 = 1.f / (1.f + expf(m1 - m0));
        int p0 = warp * 2, p1 = p0 + 1;
        g_expert[p0] = i0; g_gate[p0] = g0;
        g_expert[p1] = i1; g_gate[p1] = 1.f - g0;
        atomicAdd(&g_counts[i0], 1);
        atomicAdd(&g_counts[i1], 1);
    }
}

__global__ void scan_kernel() {
    int off = 0;
    for (int e = 0; e < NEXP; e++) { g_offs[e] = off; off += g_counts[e]; }
    g_offs[NEXP] = off;
    int nt = 0;
    for (int e = 0; e < NEXP; e++) {
        int c = g_counts[e], base = g_offs[e];
        for (int r = 0; r < c; r += BM) {
            g_tile_e[nt] = e; g_tile_r0[nt] = base + r;
            g_tile_rows[nt] = (c - r < BM) ? (c - r) : BM;
            nt++;
        }
    }
    g_ntiles = nt;
}

__global__ void scatter_kernel() {
    int p = blockIdx.x * blockDim.x + threadIdx.x;
    if (p >= NP) return;
    int e = g_expert[p];
    int row = g_offs[e] + atomicAdd(&g_fill[e], 1);
    g_pair[row] = p;
    g_pos[p] = row;
}

// ---------------- GEMM1: h = silu(x@W1)*(x@W3), bf16x3, 2 CTA/SM -------------
// smem (bf16 elems): Ah[128*40]@0 | Al@5120 | B1h[32*72]@10240 | B1l@12544 |
//   B3h@14848 | B3l@17152  -> 19456 elem = 38912 B; fp32 stage reuses (36864 B)
#define G1_SMEM 38912

__global__ __launch_bounds__(256, 2)
void gemm1_wmma(const float* __restrict__ x,
                const float* __restrict__ W1,
                const float* __restrict__ W3) {
    if ((int)blockIdx.x >= g_ntiles) return;
    __shared__ __align__(16) char sm[G1_SMEM];
    __shared__ int s_tok[128];
    __nv_bfloat16* Ah  = (__nv_bfloat16*)sm;
    __nv_bfloat16* Al  = Ah + 5120;
    __nv_bfloat16* B1h = Ah + 10240;
    __nv_bfloat16* B1l = Ah + 12544;
    __nv_bfloat16* B3h = Ah + 14848;
    __nv_bfloat16* B3l = Ah + 17152;
    float* stage = (float*)sm;

    int e    = g_tile_e[blockIdx.x];
    int row0 = g_tile_r0[blockIdx.x];
    int rows = g_tile_rows[blockIdx.x];
    int n0   = blockIdx.y * 64;
    int tid  = threadIdx.x, wid = tid >> 5;
    int wm = wid & 3, wn = wid >> 2;

    if (tid < 128) s_tok[tid] = (tid < rows) ? (g_pair[row0 + tid] >> 1) : -1;
    __syncthreads();

    const float* W1e = W1 + (size_t)e * DIM * HID;   // [K=DIM][N=HID]
    const float* W3e = W3 + (size_t)e * DIM * HID;

    wmma::fragment<wmma::accumulator, 16, 16, 16, float> acc1[2][2], acc3[2][2];
#pragma unroll
    for (int i = 0; i < 2; i++)
#pragma unroll
        for (int j = 0; j < 2; j++) {
            wmma::fill_fragment(acc1[i][j], 0.f);
            wmma::fill_fragment(acc3[i][j], 0.f);
        }

    for (int ch = 0; ch < DIM / 32; ch++) {
        int k0 = ch * 32;
        // A fill: gather fp32 rows of x, split -> Ah/Al. 128 rows x 8 float4.
#pragma unroll
        for (int p = 0; p < 4; p++) {
            int li = p * 256 + tid;
            int r = li >> 3, q = li & 7;
            int tok = s_tok[r];
            float4 v = make_float4(0.f, 0.f, 0.f, 0.f);
            if (tok >= 0)
                v = *reinterpret_cast<const float4*>(x + (size_t)tok * DIM + k0 + q * 4);
            ull hp, lp; split4(v, hp, lp);
            *reinterpret_cast<ull*>(Ah + r * 40 + q * 4) = hp;
            *reinterpret_cast<ull*>(Al + r * 40 + q * 4) = lp;
        }
        // B fill: W1 and W3 fp32 [32 k-rows][64 n-cols], split. 2 x 512 float4.
#pragma unroll
        for (int p = 0; p < 4; p++) {
            int li = p * 256 + tid;
            int t = li >> 9, rr = li & 511, r = rr >> 4, q = rr & 15;
            const float* src = t ? W3e : W1e;
            float4 v = *reinterpret_cast<const float4*>(
                src + (size_t)(k0 + r) * HID + n0 + q * 4);
            ull hp, lp; split4(v, hp, lp);
            __nv_bfloat16* dh = t ? B3h : B1h;
            __nv_bfloat16* dl = t ? B3l : B1l;
            *reinterpret_cast<ull*>(dh + r * 72 + q * 4) = hp;
            *reinterpret_cast<ull*>(dl + r * 72 + q * 4) = lp;
        }
        __syncthreads();

        // MMA: two a-phases to limit register lifetime
#pragma unroll
        for (int ks = 0; ks < 2; ks++) {
            wmma::fragment<wmma::matrix_a, 16, 16, 16, __nv_bfloat16, wmma::row_major> af[2];
            // phase 1: a = hi
#pragma unroll
            for (int i = 0; i < 2; i++)
                wmma::load_matrix_sync(af[i], Ah + (wm * 32 + i * 16) * 40 + ks * 16, 40);
#pragma unroll
            for (int j = 0; j < 2; j++) {
                int bcol = wn * 32 + j * 16;
                wmma::fragment<wmma::matrix_b, 16, 16, 16, __nv_bfloat16, wmma::row_major> bf;
                wmma::load_matrix_sync(bf, B1h + ks * 16 * 72 + bcol, 72);
#pragma unroll
                for (int i = 0; i < 2; i++) wmma::mma_sync(acc1[i][j], af[i], bf, acc1[i][j]);
                wmma::load_matrix_sync(bf, B1l + ks * 16 * 72 + bcol, 72);
#pragma unroll
                for (int i = 0; i < 2; i++) wmma::mma_sync(acc1[i][j], af[i], bf, acc1[i][j]);
                wmma::load_matrix_sync(bf, B3h + ks * 16 * 72 + bcol, 72);
#pragma unroll
                for (int i = 0; i < 2; i++) wmma::mma_sync(acc3[i][j], af[i], bf, acc3[i][j]);
                wmma::load_matrix_sync(bf, B3l + ks * 16 * 72 + bcol, 72);
#pragma unroll
                for (int i = 0; i < 2; i++) wmma::mma_sync(acc3[i][j], af[i], bf, acc3[i][j]);
            }
            // phase 2: a = lo (b hi only)
#pragma unroll
            for (int i = 0; i < 2; i++)
                wmma::load_matrix_sync(af[i], Al + (wm * 32 + i * 16) * 40 + ks * 16, 40);
#pragma unroll
            for (int j = 0; j < 2; j++) {
                int bcol = wn * 32 + j * 16;
                wmma::fragment<wmma::matrix_b, 16, 16, 16, __nv_bfloat16, wmma::row_major> bf;
                wmma::load_matrix_sync(bf, B1h + ks * 16 * 72 + bcol, 72);
#pragma unroll
                for (int i = 0; i < 2; i++) wmma::mma_sync(acc1[i][j], af[i], bf, acc1[i][j]);
                wmma::load_matrix_sync(bf, B3h + ks * 16 * 72 + bcol, 72);
#pragma unroll
                for (int i = 0; i < 2; i++) wmma::mma_sync(acc3[i][j], af[i], bf, acc3[i][j]);
            }
        }
        __syncthreads();
    }

    // epilogue: silu(z1)*z3 in-fragment, stage fp32, write SPLIT bf16 h
#pragma unroll
    for (int i = 0; i < 2; i++)
#pragma unroll
        for (int j = 0; j < 2; j++) {
#pragma unroll
            for (int t = 0; t < acc1[i][j].num_elements; t++) {
                float z = acc1[i][j].x[t];
                acc1[i][j].x[t] = z / (1.f + __expf(-z)) * acc3[i][j].x[t];
            }
            wmma::store_matrix_sync(stage + (wm * 32 + i * 16) * 72 + wn * 32 + j * 16,
                                    acc1[i][j], 72, wmma::mem_row_major);
        }
    __syncthreads();

    int row = tid >> 1, half = tid & 1;
    if (row < rows) {
        size_t ob = (size_t)(row0 + row) * HID + n0 + half * 32;
#pragma unroll
        for (int j = 0; j < 8; j++) {
            float4 v = *reinterpret_cast<const float4*>(stage + row * 72 + half * 32 + j * 4);
            ull hp, lp; split4(v, hp, lp);
            *reinterpret_cast<ull*>(&g_Hh[ob + j * 4]) = hp;
            *reinterpret_cast<ull*>(&g_Hl[ob + j * 4]) = lp;
        }
    }
}

// ---------------- GEMM2: P = h @ W2, prefetch + 2 CTA/SM, pre-split A -------
// smem (bf16): Ah[128*40]@0 | Al@5120 | Bh[32*72]@10240 | Bl@12544
//   -> 14848 elem = 29696 B; fp32 stage 36864 B
#define G2_SMEM 36864

__global__ __launch_bounds__(256, 2)
void gemm2_wmma(const float* __restrict__ W2) {
    if ((int)blockIdx.x >= g_ntiles) return;
    __shared__ __align__(16) char sm[G2_SMEM];
    __nv_bfloat16* Ah = (__nv_bfloat16*)sm;
    __nv_bfloat16* Al = Ah + 5120;
    __nv_bfloat16* Bh = Ah + 10240;
    __nv_bfloat16* Bl = Ah + 12544;
    float* stage = (float*)sm;

    int e    = g_tile_e[blockIdx.x];
    int row0 = g_tile_r0[blockIdx.x];
    int rows = g_tile_rows[blockIdx.x];
    int n0   = blockIdx.y * 64;
    int tid  = threadIdx.x, wid = tid >> 5;
    int wm = wid & 3, wn = wid >> 2;

    const float* W2e = W2 + (size_t)e * HID * DIM;   // [K=HID][N=DIM]

    int ar[2], aq[2];
#pragma unroll
    for (int p = 0; p < 2; p++) {
        int li = p * 256 + tid;
        ar[p] = li >> 2; aq[p] = li & 3;
    }
    int br[2], bq[2];
#pragma unroll
    for (int p = 0; p < 2; p++) {
        int li = p * 256 + tid;
        br[p] = li >> 4; bq[p] = li & 15;
    }

    wmma::fragment<wmma::accumulator, 16, 16, 16, float> acc[2][2];
#pragma unroll
    for (int i = 0; i < 2; i++)
#pragma unroll
        for (int j = 0; j < 2; j++) wmma::fill_fragment(acc[i][j], 0.f);

    uint4 vah[2], val[2];
    float4 vb[2];
#pragma unroll
    for (int p = 0; p < 2; p++) {
        if (ar[p] < rows) {
            size_t s = (size_t)(row0 + ar[p]) * HID + aq[p] * 8;
            vah[p] = *reinterpret_cast<const uint4*>(&g_Hh[s]);
            val[p] = *reinterpret_cast<const uint4*>(&g_Hl[s]);
        } else {
            vah[p] = make_uint4(0u, 0u, 0u, 0u);
            val[p] = make_uint4(0u, 0u, 0u, 0u);
        }
        vb[p] = *reinterpret_cast<const float4*>(W2e + (size_t)br[p] * DIM + n0 + bq[p] * 4);
    }

    for (int ch = 0; ch < HID / 32; ch++) {
#pragma unroll
        for (int p = 0; p < 2; p++) {
            *reinterpret_cast<uint4*>(Ah + ar[p] * 40 + aq[p] * 8) = vah[p];
            *reinterpret_cast<uint4*>(Al + ar[p] * 40 + aq[p] * 8) = val[p];
            ull hp, lp; split4(vb[p], hp, lp);
            *reinterpret_cast<ull*>(Bh + br[p] * 72 + bq[p] * 4) = hp;
            *reinterpret_cast<ull*>(Bl + br[p] * 72 + bq[p] * 4) = lp;
        }
        __syncthreads();

        if (ch + 1 < HID / 32) {
            int k0n = (ch + 1) * 32;
#pragma unroll
            for (int p = 0; p < 2; p++) {
                if (ar[p] < rows) {
                    size_t s = (size_t)(row0 + ar[p]) * HID + k0n + aq[p] * 8;
                    vah[p] = *reinterpret_cast<const uint4*>(&g_Hh[s]);
                    val[p] = *reinterpret_cast<const uint4*>(&g_Hl[s]);
                }
                vb[p] = *reinterpret_cast<const float4*>(
                    W2e + (size_t)(k0n + br[p]) * DIM + n0 + bq[p] * 4);
            }
        }

#pragma unroll
        for (int ks = 0; ks < 2; ks++) {
            wmma::fragment<wmma::matrix_a, 16, 16, 16, __nv_bfloat16, wmma::row_major> af[2];
#pragma unroll
            for (int i = 0; i < 2; i++)
                wmma::load_matrix_sync(af[i], Ah + (wm * 32 + i * 16) * 40 + ks * 16, 40);
#pragma unroll
            for (int j = 0; j < 2; j++) {
                int bcol = wn * 32 + j * 16;
                wmma::fragment<wmma::matrix_b, 16, 16, 16, __nv_bfloat16, wmma::row_major> bf;
                wmma::load_matrix_sync(bf, Bh + ks * 16 * 72 + bcol, 72);
#pragma unroll
                for (int i = 0; i < 2; i++) wmma::mma_sync(acc[i][j], af[i], bf, acc[i][j]);
                wmma::load_matrix_sync(bf, Bl + ks * 16 * 72 + bcol, 72);
#pragma unroll
                for (int i = 0; i < 2; i++) wmma::mma_sync(acc[i][j], af[i], bf, acc[i][j]);
            }
#pragma unroll
            for (int i = 0; i < 2; i++)
                wmma::load_matrix_sync(af[i], Al + (wm * 32 + i * 16) * 40 + ks * 16, 40);
#pragma unroll
            for (int j = 0; j < 2; j++) {
                int bcol = wn * 32 + j * 16;
                wmma::fragment<wmma::matrix_b, 16, 16, 16, __nv_bfloat16, wmma::row_major> bf;
                wmma::load_matrix_sync(bf, Bh + ks * 16 * 72 + bcol, 72);
#pragma unroll
                for (int i = 0; i < 2; i++) wmma::mma_sync(acc[i][j], af[i], bf, acc[i][j]);
            }
        }
        __syncthreads();
    }

#pragma unroll
    for (int i = 0; i < 2; i++)
#pragma unroll
        for (int j = 0; j < 2; j++)
            wmma::store_matrix_sync(stage + (wm * 32 + i * 16) * 72 + wn * 32 + j * 16,
                                    acc[i][j], 72, wmma::mem_row_major);
    __syncthreads();

    int row = tid >> 1, half = tid & 1;
    if (row < rows) {
        float* dst = g_P + (size_t)(row0 + row) * DIM + n0 + half * 32;
#pragma unroll
        for (int j = 0; j < 8; j++)
            *reinterpret_cast<float4*>(dst + j * 4) =
                *reinterpret_cast<const float4*>(stage + row * 72 + half * 32 + j * 4);
    }
}

// ---------------- combine (verbatim) ------------------------------------------
__global__ void combine_kernel(float* __restrict__ out) {
    int t = blockIdx.x;
    int d = threadIdx.x * 4;
    int pb = t * 2;
    int r0 = g_pos[pb], r1 = g_pos[pb + 1];
    float g0 = g_gate[pb], g1 = g_gate[pb + 1];
    float4 v0 = *reinterpret_cast<const float4*>(g_P + (size_t)r0 * DIM + d);
    float4 v1 = *reinterpret_cast<const float4*>(g_P + (size_t)r1 * DIM + d);
    float4 o;
    o.x = g0 * v0.x + g1 * v1.x;
    o.y = g0 * v0.y + g1 * v1.y;
    o.z = g0 * v0.z + g1 * v1.z;
    o.w = g0 * v0.w + g1 * v1.w;
    *reinterpret_cast<float4*>(out + (size_t)t * DIM + d) = o;
}

// ---------------- launch (same 7-launch sequence) -----------------------------
extern "C" void kernel_launch(void* const* d_in, const int* in_sizes, int n_in,
                              void* d_out, int out_size) {
    (void)in_sizes; (void)n_in; (void)out_size;
    const float* x  = (const float*)d_in[0];
    const float* Wr = (const float*)d_in[1];
    const float* W1 = (const float*)d_in[2];
    const float* W2 = (const float*)d_in[3];
    const float* W3 = (const float*)d_in[4];
    float* out = (float*)d_out;

    init_kernel<<<1, 32>>>();
    router_kernel<<<T_TOK / 8, 256>>>(x, Wr);
    scan_kernel<<<1, 1>>>();
    scatter_kernel<<<NP / 256, 256>>>();
    gemm1_wmma<<<dim3(MAXTILES, HID / 64), 256>>>(x, W1, W3);
    gemm2_wmma<<<dim3(MAXTILES, DIM / 64), 256>>>(W2);
    combine_kernel<<<T_TOK, 256>>>(out);
}

// round 9
// speedup vs baseline: 1.7506x; 1.0871x over previous
#include <cuda_runtime.h>
#include <cuda_bf16.h>
#include <mma.h>
#include <cstdint>

using namespace nvcuda;
typedef unsigned long long ull;

#define T_TOK 4096
#define DIM   1024
#define HID   2048
#define NEXP  8
#define NP    (T_TOK * 2)
#define BM    128
#define MAXTILES (NP / BM + NEXP)   // 72

// ---------------- scratch (<=100 MB total; no prep kernels) ------------------
__device__ int   g_pair[NP];
__device__ int   g_pos[NP];
__device__ float g_gate[NP];
__device__ int   g_expert[NP];
__device__ int   g_counts[NEXP];
__device__ int   g_fill[NEXP];
__device__ int   g_offs[NEXP + 1];
__device__ int   g_tile_e[MAXTILES];
__device__ int   g_tile_r0[MAXTILES];
__device__ int   g_tile_rows[MAXTILES];
__device__ int   g_ntiles;
__device__ float g_P[(size_t)NP * DIM];               // 32 MB
__device__ __nv_bfloat16 g_Hh[(size_t)NP * HID];      // 32 MB (hidden, hi)
__device__ __nv_bfloat16 g_Hl[(size_t)NP * HID];      // 32 MB (hidden, lo)

// ---------------- helpers ----------------------------------------------------
__device__ __forceinline__ void split_bf(float v, uint16_t& h, uint16_t& l) {
    __nv_bfloat16 bh = __float2bfloat16_rn(v);
    float fh = __bfloat162float(bh);
    __nv_bfloat16 bl = __float2bfloat16_rn(v - fh);
    h = __bfloat16_as_ushort(bh);
    l = __bfloat16_as_ushort(bl);
}
__device__ __forceinline__ void split4(float4 v, ull& hp, ull& lp) {
    uint16_t h0, h1, h2, h3, l0, l1, l2, l3;
    split_bf(v.x, h0, l0); split_bf(v.y, h1, l1);
    split_bf(v.z, h2, l2); split_bf(v.w, h3, l3);
    hp = (ull)h0 | ((ull)h1 << 16) | ((ull)h2 << 32) | ((ull)h3 << 48);
    lp = (ull)l0 | ((ull)l1 << 16) | ((ull)l2 << 32) | ((ull)l3 << 48);
}

// ---------------- routing path (verbatim, proven) -----------------------------
__global__ void init_kernel() {
    int t = threadIdx.x;
    if (t < NEXP) { g_counts[t] = 0; g_fill[t] = 0; }
}

__global__ void router_kernel(const float* __restrict__ x,
                              const float* __restrict__ Wr) {
    int warp = (blockIdx.x * blockDim.x + threadIdx.x) >> 5;
    int lane = threadIdx.x & 31;
    if (warp >= T_TOK) return;
    const float* xr = x + (size_t)warp * DIM;
    float acc[NEXP];
#pragma unroll
    for (int e = 0; e < NEXP; e++) acc[e] = 0.f;
    for (int d = lane; d < DIM; d += 32) {
        float xv = xr[d];
        const float4* w = reinterpret_cast<const float4*>(Wr + (size_t)d * NEXP);
        float4 w0 = w[0], w1 = w[1];
        acc[0] = fmaf(xv, w0.x, acc[0]); acc[1] = fmaf(xv, w0.y, acc[1]);
        acc[2] = fmaf(xv, w0.z, acc[2]); acc[3] = fmaf(xv, w0.w, acc[3]);
        acc[4] = fmaf(xv, w1.x, acc[4]); acc[5] = fmaf(xv, w1.y, acc[5]);
        acc[6] = fmaf(xv, w1.z, acc[6]); acc[7] = fmaf(xv, w1.w, acc[7]);
    }
#pragma unroll
    for (int off = 16; off > 0; off >>= 1)
#pragma unroll
        for (int e = 0; e < NEXP; e++)
            acc[e] += __shfl_down_sync(0xffffffffu, acc[e], off);
    if (lane == 0) {
        int i0 = 0; float m0 = acc[0];
#pragma unroll
        for (int e = 1; e < NEXP; e++)
            if (acc[e] > m0) { m0 = acc[e]; i0 = e; }
        int i1 = -1; float m1 = -3.4e38f;
#pragma unroll
        for (int e = 0; e < NEXP; e++)
            if (e != i0 && acc[e] > m1) { m1 = acc[e]; i1 = e; }
        float g0 = 1.f / (1.f + expf(m1 - m0));
        int p0 = warp * 2, p1 = p0 + 1;
        g_expert[p0] = i0; g_gate[p0] = g0;
        g_expert[p1] = i1; g_gate[p1] = 1.f - g0;
        atomicAdd(&g_counts[i0], 1);
        atomicAdd(&g_counts[i1], 1);
    }
}

__global__ void scan_kernel() {
    int off = 0;
    for (int e = 0; e < NEXP; e++) { g_offs[e] = off; off += g_counts[e]; }
    g_offs[NEXP] = off;
    int nt = 0;
    for (int e = 0; e < NEXP; e++) {
        int c = g_counts[e], base = g_offs[e];
        for (int r = 0; r < c; r += BM) {
            g_tile_e[nt] = e; g_tile_r0[nt] = base + r;
            g_tile_rows[nt] = (c - r < BM) ? (c - r) : BM;
            nt++;
        }
    }
    g_ntiles = nt;
}

__global__ void scatter_kernel() {
    int p = blockIdx.x * blockDim.x + threadIdx.x;
    if (p >= NP) return;
    int e = g_expert[p];
    int row = g_offs[e] + atomicAdd(&g_fill[e], 1);
    g_pair[row] = p;
    g_pos[p] = row;
}

// ---------------- GEMM1: h = silu(x@W1)*(x@W3), bf16x3, 2 CTA/SM (R8 verbatim)
#define G1_SMEM 38912

__global__ __launch_bounds__(256, 2)
void gemm1_wmma(const float* __restrict__ x,
                const float* __restrict__ W1,
                const float* __restrict__ W3) {
    if ((int)blockIdx.x >= g_ntiles) return;
    __shared__ __align__(16) char sm[G1_SMEM];
    __shared__ int s_tok[128];
    __nv_bfloat16* Ah  = (__nv_bfloat16*)sm;
    __nv_bfloat16* Al  = Ah + 5120;
    __nv_bfloat16* B1h = Ah + 10240;
    __nv_bfloat16* B1l = Ah + 12544;
    __nv_bfloat16* B3h = Ah + 14848;
    __nv_bfloat16* B3l = Ah + 17152;
    float* stage = (float*)sm;

    int e    = g_tile_e[blockIdx.x];
    int row0 = g_tile_r0[blockIdx.x];
    int rows = g_tile_rows[blockIdx.x];
    int n0   = blockIdx.y * 64;
    int tid  = threadIdx.x, wid = tid >> 5;
    int wm = wid & 3, wn = wid >> 2;

    if (tid < 128) s_tok[tid] = (tid < rows) ? (g_pair[row0 + tid] >> 1) : -1;
    __syncthreads();

    const float* W1e = W1 + (size_t)e * DIM * HID;
    const float* W3e = W3 + (size_t)e * DIM * HID;

    wmma::fragment<wmma::accumulator, 16, 16, 16, float> acc1[2][2], acc3[2][2];
#pragma unroll
    for (int i = 0; i < 2; i++)
#pragma unroll
        for (int j = 0; j < 2; j++) {
            wmma::fill_fragment(acc1[i][j], 0.f);
            wmma::fill_fragment(acc3[i][j], 0.f);
        }

    for (int ch = 0; ch < DIM / 32; ch++) {
        int k0 = ch * 32;
#pragma unroll
        for (int p = 0; p < 4; p++) {
            int li = p * 256 + tid;
            int r = li >> 3, q = li & 7;
            int tok = s_tok[r];
            float4 v = make_float4(0.f, 0.f, 0.f, 0.f);
            if (tok >= 0)
                v = *reinterpret_cast<const float4*>(x + (size_t)tok * DIM + k0 + q * 4);
            ull hp, lp; split4(v, hp, lp);
            *reinterpret_cast<ull*>(Ah + r * 40 + q * 4) = hp;
            *reinterpret_cast<ull*>(Al + r * 40 + q * 4) = lp;
        }
#pragma unroll
        for (int p = 0; p < 4; p++) {
            int li = p * 256 + tid;
            int t = li >> 9, rr = li & 511, r = rr >> 4, q = rr & 15;
            const float* src = t ? W3e : W1e;
            float4 v = *reinterpret_cast<const float4*>(
                src + (size_t)(k0 + r) * HID + n0 + q * 4);
            ull hp, lp; split4(v, hp, lp);
            __nv_bfloat16* dh = t ? B3h : B1h;
            __nv_bfloat16* dl = t ? B3l : B1l;
            *reinterpret_cast<ull*>(dh + r * 72 + q * 4) = hp;
            *reinterpret_cast<ull*>(dl + r * 72 + q * 4) = lp;
        }
        __syncthreads();

#pragma unroll
        for (int ks = 0; ks < 2; ks++) {
            wmma::fragment<wmma::matrix_a, 16, 16, 16, __nv_bfloat16, wmma::row_major> af[2];
#pragma unroll
            for (int i = 0; i < 2; i++)
                wmma::load_matrix_sync(af[i], Ah + (wm * 32 + i * 16) * 40 + ks * 16, 40);
#pragma unroll
            for (int j = 0; j < 2; j++) {
                int bcol = wn * 32 + j * 16;
                wmma::fragment<wmma::matrix_b, 16, 16, 16, __nv_bfloat16, wmma::row_major> bf;
                wmma::load_matrix_sync(bf, B1h + ks * 16 * 72 + bcol, 72);
#pragma unroll
                for (int i = 0; i < 2; i++) wmma::mma_sync(acc1[i][j], af[i], bf, acc1[i][j]);
                wmma::load_matrix_sync(bf, B1l + ks * 16 * 72 + bcol, 72);
#pragma unroll
                for (int i = 0; i < 2; i++) wmma::mma_sync(acc1[i][j], af[i], bf, acc1[i][j]);
                wmma::load_matrix_sync(bf, B3h + ks * 16 * 72 + bcol, 72);
#pragma unroll
                for (int i = 0; i < 2; i++) wmma::mma_sync(acc3[i][j], af[i], bf, acc3[i][j]);
                wmma::load_matrix_sync(bf, B3l + ks * 16 * 72 + bcol, 72);
#pragma unroll
                for (int i = 0; i < 2; i++) wmma::mma_sync(acc3[i][j], af[i], bf, acc3[i][j]);
            }
#pragma unroll
            for (int i = 0; i < 2; i++)
                wmma::load_matrix_sync(af[i], Al + (wm * 32 + i * 16) * 40 + ks * 16, 40);
#pragma unroll
            for (int j = 0; j < 2; j++) {
                int bcol = wn * 32 + j * 16;
                wmma::fragment<wmma::matrix_b, 16, 16, 16, __nv_bfloat16, wmma::row_major> bf;
                wmma::load_matrix_sync(bf, B1h + ks * 16 * 72 + bcol, 72);
#pragma unroll
                for (int i = 0; i < 2; i++) wmma::mma_sync(acc1[i][j], af[i], bf, acc1[i][j]);
                wmma::load_matrix_sync(bf, B3h + ks * 16 * 72 + bcol, 72);
#pragma unroll
                for (int i = 0; i < 2; i++) wmma::mma_sync(acc3[i][j], af[i], bf, acc3[i][j]);
            }
        }
        __syncthreads();
    }

#pragma unroll
    for (int i = 0; i < 2; i++)
#pragma unroll
        for (int j = 0; j < 2; j++) {
#pragma unroll
            for (int t = 0; t < acc1[i][j].num_elements; t++) {
                float z = acc1[i][j].x[t];
                acc1[i][j].x[t] = z / (1.f + __expf(-z)) * acc3[i][j].x[t];
            }
            wmma::store_matrix_sync(stage + (wm * 32 + i * 16) * 72 + wn * 32 + j * 16,
                                    acc1[i][j], 72, wmma::mem_row_major);
        }
    __syncthreads();

    int row = tid >> 1, half = tid & 1;
    if (row < rows) {
        size_t ob = (size_t)(row0 + row) * HID + n0 + half * 32;
#pragma unroll
        for (int j = 0; j < 8; j++) {
            float4 v = *reinterpret_cast<const float4*>(stage + row * 72 + half * 32 + j * 4);
            ull hp, lp; split4(v, hp, lp);
            *reinterpret_cast<ull*>(&g_Hh[ob + j * 4]) = hp;
            *reinterpret_cast<ull*>(&g_Hl[ob + j * 4]) = lp;
        }
    }
}

// ---------------- GEMM2: P = h @ W2, 128x128 tiles, 2 CTA/SM -----------------
// smem (bf16 elems): Ah[128*40]@0 | Al@5120 | Bh[32*136]@10240 | Bl@14592
//   -> 18944 elem = 37888 B; fp32 stage [128][72] = 36864 B reuses
#define G2_SMEM 37888

__global__ __launch_bounds__(256, 2)
void gemm2_wmma(const float* __restrict__ W2) {
    if ((int)blockIdx.x >= g_ntiles) return;
    __shared__ __align__(16) char sm[G2_SMEM];
    __nv_bfloat16* Ah = (__nv_bfloat16*)sm;
    __nv_bfloat16* Al = Ah + 5120;
    __nv_bfloat16* Bh = Ah + 10240;
    __nv_bfloat16* Bl = Ah + 14592;
    float* stage = (float*)sm;

    int e    = g_tile_e[blockIdx.x];
    int row0 = g_tile_r0[blockIdx.x];
    int rows = g_tile_rows[blockIdx.x];
    int n0   = blockIdx.y * 128;
    int tid  = threadIdx.x, wid = tid >> 5;
    int wm = wid & 3, wn = wid >> 2;     // 4 m-groups x 2 n-groups(64 cols each)

    const float* W2e = W2 + (size_t)e * HID * DIM;   // [K=HID][N=DIM]

    wmma::fragment<wmma::accumulator, 16, 16, 16, float> acc[2][4];
#pragma unroll
    for (int i = 0; i < 2; i++)
#pragma unroll
        for (int j = 0; j < 4; j++) wmma::fill_fragment(acc[i][j], 0.f);

    for (int ch = 0; ch < HID / 32; ch++) {
        int k0 = ch * 32;
        // A fill: 128 rows x 32 bf16 (hi,lo) = 2 x 512 uint4
#pragma unroll
        for (int p = 0; p < 2; p++) {
            int li = p * 256 + tid;
            int r = li >> 2, q = li & 3;
            uint4 vh = make_uint4(0u, 0u, 0u, 0u), vl = vh;
            if (r < rows) {
                size_t s = (size_t)(row0 + r) * HID + k0 + q * 8;
                vh = *reinterpret_cast<const uint4*>(&g_Hh[s]);
                vl = *reinterpret_cast<const uint4*>(&g_Hl[s]);
            }
            *reinterpret_cast<uint4*>(Ah + r * 40 + q * 8) = vh;
            *reinterpret_cast<uint4*>(Al + r * 40 + q * 8) = vl;
        }
        // B fill: 32 k-rows x 128 n-cols fp32, split. 1024 float4 = 4/thread.
#pragma unroll
        for (int p = 0; p < 4; p++) {
            int li = p * 256 + tid;
            int r = li >> 5, q = li & 31;
            float4 v = *reinterpret_cast<const float4*>(
                W2e + (size_t)(k0 + r) * DIM + n0 + q * 4);
            ull hp, lp; split4(v, hp, lp);
            *reinterpret_cast<ull*>(Bh + r * 136 + q * 4) = hp;
            *reinterpret_cast<ull*>(Bl + r * 136 + q * 4) = lp;
        }
        __syncthreads();

#pragma unroll
        for (int ks = 0; ks < 2; ks++) {
            wmma::fragment<wmma::matrix_a, 16, 16, 16, __nv_bfloat16, wmma::row_major> af[2];
#pragma unroll
            for (int i = 0; i < 2; i++)
                wmma::load_matrix_sync(af[i], Ah + (wm * 32 + i * 16) * 40 + ks * 16, 40);
#pragma unroll
            for (int j = 0; j < 4; j++) {
                int bcol = wn * 64 + j * 16;
                wmma::fragment<wmma::matrix_b, 16, 16, 16, __nv_bfloat16, wmma::row_major> bf;
                wmma::load_matrix_sync(bf, Bh + ks * 16 * 136 + bcol, 136);
#pragma unroll
                for (int i = 0; i < 2; i++) wmma::mma_sync(acc[i][j], af[i], bf, acc[i][j]);
                wmma::load_matrix_sync(bf, Bl + ks * 16 * 136 + bcol, 136);
#pragma unroll
                for (int i = 0; i < 2; i++) wmma::mma_sync(acc[i][j], af[i], bf, acc[i][j]);
            }
#pragma unroll
            for (int i = 0; i < 2; i++)
                wmma::load_matrix_sync(af[i], Al + (wm * 32 + i * 16) * 40 + ks * 16, 40);
#pragma unroll
            for (int j = 0; j < 4; j++) {
                int bcol = wn * 64 + j * 16;
                wmma::fragment<wmma::matrix_b, 16, 16, 16, __nv_bfloat16, wmma::row_major> bf;
                wmma::load_matrix_sync(bf, Bh + ks * 16 * 136 + bcol, 136);
#pragma unroll
                for (int i = 0; i < 2; i++) wmma::mma_sync(acc[i][j], af[i], bf, acc[i][j]);
            }
        }
        __syncthreads();
    }

    if (rows == BM) {
        // full tile: store fragments directly to global (ld = DIM)
#pragma unroll
        for (int i = 0; i < 2; i++)
#pragma unroll
            for (int j = 0; j < 4; j++)
                wmma::store_matrix_sync(
                    g_P + (size_t)(row0 + wm * 32 + i * 16) * DIM + n0 + wn * 64 + j * 16,
                    acc[i][j], DIM, wmma::mem_row_major);
    } else {
        // boundary tile: two staged passes of 64 columns with row guard
#pragma unroll
        for (int half = 0; half < 2; half++) {
            if (wn == half) {
#pragma unroll
                for (int i = 0; i < 2; i++)
#pragma unroll
                    for (int j = 0; j < 4; j++)
                        wmma::store_matrix_sync(stage + (wm * 32 + i * 16) * 72 + j * 16,
                                                acc[i][j], 72, wmma::mem_row_major);
            }
            __syncthreads();
            int row = tid >> 1, h2 = tid & 1;
            if (row < rows) {
                float* dst = g_P + (size_t)(row0 + row) * DIM + n0 + half * 64 + h2 * 32;
#pragma unroll
                for (int j = 0; j < 8; j++)
                    *reinterpret_cast<float4*>(dst + j * 4) =
                        *reinterpret_cast<const float4*>(stage + row * 72 + h2 * 32 + j * 4);
            }
            __syncthreads();
        }
    }
}

// ---------------- combine (verbatim) ------------------------------------------
__global__ void combine_kernel(float* __restrict__ out) {
    int t = blockIdx.x;
    int d = threadIdx.x * 4;
    int pb = t * 2;
    int r0 = g_pos[pb], r1 = g_pos[pb + 1];
    float g0 = g_gate[pb], g1 = g_gate[pb + 1];
    float4 v0 = *reinterpret_cast<const float4*>(g_P + (size_t)r0 * DIM + d);
    float4 v1 = *reinterpret_cast<const float4*>(g_P + (size_t)r1 * DIM + d);
    float4 o;
    o.x = g0 * v0.x + g1 * v1.x;
    o.y = g0 * v0.y + g1 * v1.y;
    o.z = g0 * v0.z + g1 * v1.z;
    o.w = g0 * v0.w + g1 * v1.w;
    *reinterpret_cast<float4*>(out + (size_t)t * DIM + d) = o;
}

// ---------------- launch ------------------------------------------------------
extern "C" void kernel_launch(void* const* d_in, const int* in_sizes, int n_in,
                              void* d_out, int out_size) {
    (void)in_sizes; (void)n_in; (void)out_size;
    const float* x  = (const float*)d_in[0];
    const float* Wr = (const float*)d_in[1];
    const float* W1 = (const float*)d_in[2];
    const float* W2 = (const float*)d_in[3];
    const float* W3 = (const float*)d_in[4];
    float* out = (float*)d_out;

    init_kernel<<<1, 32>>>();
    router_kernel<<<T_TOK / 8, 256>>>(x, Wr);
    scan_kernel<<<1, 1>>>();
    scatter_kernel<<<NP / 256, 256>>>();
    gemm1_wmma<<<dim3(MAXTILES, HID / 64), 256>>>(x, W1, W3);
    gemm2_wmma<<<dim3(MAXTILES, DIM / 128), 256>>>(W2);
    combine_kernel<<<T_TOK, 256>>>(out);
}

// round 10
// speedup vs baseline: 1.8858x; 1.0772x over previous
#include <cuda_runtime.h>
#include <cuda_bf16.h>
#include <mma.h>
#include <cstdint>

using namespace nvcuda;
typedef unsigned long long ull;

#define T_TOK 4096
#define DIM   1024
#define HID   2048
#define NEXP  8
#define NP    (T_TOK * 2)
#define BM    128
#define MAXTILES (NP / BM + NEXP)   // 72

// ---------------- scratch (112 MB total) -------------------------------------
__device__ int   g_pair[NP];
__device__ int   g_pos[NP];
__device__ float g_gate[NP];
__device__ int   g_expert[NP];
__device__ int   g_counts[NEXP];
__device__ int   g_fill[NEXP];
__device__ int   g_offs[NEXP + 1];
__device__ int   g_tile_e[MAXTILES];
__device__ int   g_tile_r0[MAXTILES];
__device__ int   g_tile_rows[MAXTILES];
__device__ int   g_ntiles;
__device__ float g_P[(size_t)NP * DIM];               // 32 MB
__device__ __nv_bfloat16 g_Hh[(size_t)NP * HID];      // 32 MB
__device__ __nv_bfloat16 g_Hl[(size_t)NP * HID];      // 32 MB
__device__ __nv_bfloat16 g_Xh[(size_t)T_TOK * DIM];   // 8 MB (pre-split x)
__device__ __nv_bfloat16 g_Xl[(size_t)T_TOK * DIM];   // 8 MB

// ---------------- truncation split (PRMT prefix) -----------------------------
// h = top-16-bit prefix of f32 (exact), l = prefix of (v - h). residual 2^-16|v|
__device__ __forceinline__ void split4t(float4 v, ull& hp, ull& lp) {
    uint32_t bx = __float_as_uint(v.x), by = __float_as_uint(v.y),
             bz = __float_as_uint(v.z), bw = __float_as_uint(v.w);
    uint32_t h01 = __byte_perm(bx, by, 0x7632);
    uint32_t h23 = __byte_perm(bz, bw, 0x7632);
    float rx = v.x - __uint_as_float(bx & 0xFFFF0000u);
    float ry = v.y - __uint_as_float(by & 0xFFFF0000u);
    float rz = v.z - __uint_as_float(bz & 0xFFFF0000u);
    float rw = v.w - __uint_as_float(bw & 0xFFFF0000u);
    uint32_t l01 = __byte_perm(__float_as_uint(rx), __float_as_uint(ry), 0x7632);
    uint32_t l23 = __byte_perm(__float_as_uint(rz), __float_as_uint(rw), 0x7632);
    hp = (ull)h01 | ((ull)h23 << 32);
    lp = (ull)l01 | ((ull)l23 << 32);
}

// ---------------- routing path (verbatim, proven) -----------------------------
__global__ void init_kernel() {
    int t = threadIdx.x;
    if (t < NEXP) { g_counts[t] = 0; g_fill[t] = 0; }
}

__global__ void router_kernel(const float* __restrict__ x,
                              const float* __restrict__ Wr) {
    int warp = (blockIdx.x * blockDim.x + threadIdx.x) >> 5;
    int lane = threadIdx.x & 31;
    if (warp >= T_TOK) return;
    const float* xr = x + (size_t)warp * DIM;
    float acc[NEXP];
#pragma unroll
    for (int e = 0; e < NEXP; e++) acc[e] = 0.f;
    for (int d = lane; d < DIM; d += 32) {
        float xv = xr[d];
        const float4* w = reinterpret_cast<const float4*>(Wr + (size_t)d * NEXP);
        float4 w0 = w[0], w1 = w[1];
        acc[0] = fmaf(xv, w0.x, acc[0]); acc[1] = fmaf(xv, w0.y, acc[1]);
        acc[2] = fmaf(xv, w0.z, acc[2]); acc[3] = fmaf(xv, w0.w, acc[3]);
        acc[4] = fmaf(xv, w1.x, acc[4]); acc[5] = fmaf(xv, w1.y, acc[5]);
        acc[6] = fmaf(xv, w1.z, acc[6]); acc[7] = fmaf(xv, w1.w, acc[7]);
    }
#pragma unroll
    for (int off = 16; off > 0; off >>= 1)
#pragma unroll
        for (int e = 0; e < NEXP; e++)
            acc[e] += __shfl_down_sync(0xffffffffu, acc[e], off);
    if (lane == 0) {
        int i0 = 0; float m0 = acc[0];
#pragma unroll
        for (int e = 1; e < NEXP; e++)
            if (acc[e] > m0) { m0 = acc[e]; i0 = e; }
        int i1 = -1; float m1 = -3.4e38f;
#pragma unroll
        for (int e = 0; e < NEXP; e++)
            if (e != i0 && acc[e] > m1) { m1 = acc[e]; i1 = e; }
        float g0 = 1.f / (1.f + expf(m1 - m0));
        int p0 = warp * 2, p1 = p0 + 1;
        g_expert[p0] = i0; g_gate[p0] = g0;
        g_expert[p1] = i1; g_gate[p1] = 1.f - g0;
        atomicAdd(&g_counts[i0], 1);
        atomicAdd(&g_counts[i1], 1);
    }
}

__global__ void scan_kernel() {
    int off = 0;
    for (int e = 0; e < NEXP; e++) { g_offs[e] = off; off += g_counts[e]; }
    g_offs[NEXP] = off;
    int nt = 0;
    for (int e = 0; e < NEXP; e++) {
        int c = g_counts[e], base = g_offs[e];
        for (int r = 0; r < c; r += BM) {
            g_tile_e[nt] = e; g_tile_r0[nt] = base + r;
            g_tile_rows[nt] = (c - r < BM) ? (c - r) : BM;
            nt++;
        }
    }
    g_ntiles = nt;
}

__global__ void scatter_kernel() {
    int p = blockIdx.x * blockDim.x + threadIdx.x;
    if (p >= NP) return;
    int e = g_expert[p];
    int row = g_offs[e] + atomicAdd(&g_fill[e], 1);
    g_pair[row] = p;
    g_pos[p] = row;
}

// ---------------- x pre-split (elementwise; mirrors proven structure) --------
__global__ void x_split_kernel(const float* __restrict__ x) {
    size_t i = ((size_t)blockIdx.x * 256 + threadIdx.x) * 4;
    float4 v = *reinterpret_cast<const float4*>(x + i);
    ull hp, lp; split4t(v, hp, lp);
    *reinterpret_cast<ull*>(&g_Xh[i]) = hp;
    *reinterpret_cast<ull*>(&g_Xl[i]) = lp;
}

// ---------------- GEMM1: h = silu(x@W1)*(x@W3), bf16x3, 2 CTA/SM -------------
#define G1_SMEM 38912

__global__ __launch_bounds__(256, 2)
void gemm1_wmma(const float* __restrict__ W1,
                const float* __restrict__ W3) {
    if ((int)blockIdx.x >= g_ntiles) return;
    __shared__ __align__(16) char sm[G1_SMEM];
    __shared__ int s_tok[128];
    __nv_bfloat16* Ah  = (__nv_bfloat16*)sm;
    __nv_bfloat16* Al  = Ah + 5120;
    __nv_bfloat16* B1h = Ah + 10240;
    __nv_bfloat16* B1l = Ah + 12544;
    __nv_bfloat16* B3h = Ah + 14848;
    __nv_bfloat16* B3l = Ah + 17152;
    float* stage = (float*)sm;

    int e    = g_tile_e[blockIdx.x];
    int row0 = g_tile_r0[blockIdx.x];
    int rows = g_tile_rows[blockIdx.x];
    int n0   = blockIdx.y * 64;
    int tid  = threadIdx.x, wid = tid >> 5;
    int wm = wid & 3, wn = wid >> 2;

    if (tid < 128) s_tok[tid] = (tid < rows) ? (g_pair[row0 + tid] >> 1) : -1;
    __syncthreads();

    const float* W1e = W1 + (size_t)e * DIM * HID;
    const float* W3e = W3 + (size_t)e * DIM * HID;

    wmma::fragment<wmma::accumulator, 16, 16, 16, float> acc1[2][2], acc3[2][2];
#pragma unroll
    for (int i = 0; i < 2; i++)
#pragma unroll
        for (int j = 0; j < 2; j++) {
            wmma::fill_fragment(acc1[i][j], 0.f);
            wmma::fill_fragment(acc3[i][j], 0.f);
        }

    for (int ch = 0; ch < DIM / 32; ch++) {
        int k0 = ch * 32;
        // A fill: pre-split bf16 copies. 2 buffers x 512 uint4 = 4/thread.
#pragma unroll
        for (int p = 0; p < 4; p++) {
            int li = p * 256 + tid;
            int hl = li >> 9, r = (li >> 2) & 127, q = li & 3;
            int tok = s_tok[r];
            uint4 v = make_uint4(0u, 0u, 0u, 0u);
            const __nv_bfloat16* src = hl ? g_Xl : g_Xh;
            if (tok >= 0)
                v = *reinterpret_cast<const uint4*>(src + (size_t)tok * DIM + k0 + q * 8);
            *reinterpret_cast<uint4*>((hl ? Al : Ah) + r * 40 + q * 8) = v;
        }
        // B fill: W1 and W3 fp32 [32 k-rows][64 n-cols], trunc-split.
#pragma unroll
        for (int p = 0; p < 4; p++) {
            int li = p * 256 + tid;
            int t = li >> 9, rr = li & 511, r = rr >> 4, q = rr & 15;
            const float* src = t ? W3e : W1e;
            float4 v = *reinterpret_cast<const float4*>(
                src + (size_t)(k0 + r) * HID + n0 + q * 4);
            ull hp, lp; split4t(v, hp, lp);
            __nv_bfloat16* dh = t ? B3h : B1h;
            __nv_bfloat16* dl = t ? B3l : B1l;
            *reinterpret_cast<ull*>(dh + r * 72 + q * 4) = hp;
            *reinterpret_cast<ull*>(dl + r * 72 + q * 4) = lp;
        }
        __syncthreads();

#pragma unroll
        for (int ks = 0; ks < 2; ks++) {
            wmma::fragment<wmma::matrix_a, 16, 16, 16, __nv_bfloat16, wmma::row_major> af[2];
#pragma unroll
            for (int i = 0; i < 2; i++)
                wmma::load_matrix_sync(af[i], Ah + (wm * 32 + i * 16) * 40 + ks * 16, 40);
#pragma unroll
            for (int j = 0; j < 2; j++) {
                int bcol = wn * 32 + j * 16;
                wmma::fragment<wmma::matrix_b, 16, 16, 16, __nv_bfloat16, wmma::row_major> bf;
                wmma::load_matrix_sync(bf, B1h + ks * 16 * 72 + bcol, 72);
#pragma unroll
                for (int i = 0; i < 2; i++) wmma::mma_sync(acc1[i][j], af[i], bf, acc1[i][j]);
                wmma::load_matrix_sync(bf, B1l + ks * 16 * 72 + bcol, 72);
#pragma unroll
                for (int i = 0; i < 2; i++) wmma::mma_sync(acc1[i][j], af[i], bf, acc1[i][j]);
                wmma::load_matrix_sync(bf, B3h + ks * 16 * 72 + bcol, 72);
#pragma unroll
                for (int i = 0; i < 2; i++) wmma::mma_sync(acc3[i][j], af[i], bf, acc3[i][j]);
                wmma::load_matrix_sync(bf, B3l + ks * 16 * 72 + bcol, 72);
#pragma unroll
                for (int i = 0; i < 2; i++) wmma::mma_sync(acc3[i][j], af[i], bf, acc3[i][j]);
            }
#pragma unroll
            for (int i = 0; i < 2; i++)
                wmma::load_matrix_sync(af[i], Al + (wm * 32 + i * 16) * 40 + ks * 16, 40);
#pragma unroll
            for (int j = 0; j < 2; j++) {
                int bcol = wn * 32 + j * 16;
                wmma::fragment<wmma::matrix_b, 16, 16, 16, __nv_bfloat16, wmma::row_major> bf;
                wmma::load_matrix_sync(bf, B1h + ks * 16 * 72 + bcol, 72);
#pragma unroll
                for (int i = 0; i < 2; i++) wmma::mma_sync(acc1[i][j], af[i], bf, acc1[i][j]);
                wmma::load_matrix_sync(bf, B3h + ks * 16 * 72 + bcol, 72);
#pragma unroll
                for (int i = 0; i < 2; i++) wmma::mma_sync(acc3[i][j], af[i], bf, acc3[i][j]);
            }
        }
        __syncthreads();
    }

#pragma unroll
    for (int i = 0; i < 2; i++)
#pragma unroll
        for (int j = 0; j < 2; j++) {
#pragma unroll
            for (int t = 0; t < acc1[i][j].num_elements; t++) {
                float z = acc1[i][j].x[t];
                acc1[i][j].x[t] = z / (1.f + __expf(-z)) * acc3[i][j].x[t];
            }
            wmma::store_matrix_sync(stage + (wm * 32 + i * 16) * 72 + wn * 32 + j * 16,
                                    acc1[i][j], 72, wmma::mem_row_major);
        }
    __syncthreads();

    int row = tid >> 1, half = tid & 1;
    if (row < rows) {
        size_t ob = (size_t)(row0 + row) * HID + n0 + half * 32;
#pragma unroll
        for (int j = 0; j < 8; j++) {
            float4 v = *reinterpret_cast<const float4*>(stage + row * 72 + half * 32 + j * 4);
            ull hp, lp; split4t(v, hp, lp);
            *reinterpret_cast<ull*>(&g_Hh[ob + j * 4]) = hp;
            *reinterpret_cast<ull*>(&g_Hl[ob + j * 4]) = lp;
        }
    }
}

// ---------------- GEMM2: P = h @ W2, 128x128 tiles, 2 CTA/SM (R9 + trunc-split)
#define G2_SMEM 37888

__global__ __launch_bounds__(256, 2)
void gemm2_wmma(const float* __restrict__ W2) {
    if ((int)blockIdx.x >= g_ntiles) return;
    __shared__ __align__(16) char sm[G2_SMEM];
    __nv_bfloat16* Ah = (__nv_bfloat16*)sm;
    __nv_bfloat16* Al = Ah + 5120;
    __nv_bfloat16* Bh = Ah + 10240;
    __nv_bfloat16* Bl = Ah + 14592;
    float* stage = (float*)sm;

    int e    = g_tile_e[blockIdx.x];
    int row0 = g_tile_r0[blockIdx.x];
    int rows = g_tile_rows[blockIdx.x];
    int n0   = blockIdx.x ? blockIdx.y * 128 : blockIdx.y * 128;  // keep simple
    int tid  = threadIdx.x, wid = tid >> 5;
    int wm = wid & 3, wn = wid >> 2;

    const float* W2e = W2 + (size_t)e * HID * DIM;

    wmma::fragment<wmma::accumulator, 16, 16, 16, float> acc[2][4];
#pragma unroll
    for (int i = 0; i < 2; i++)
#pragma unroll
        for (int j = 0; j < 4; j++) wmma::fill_fragment(acc[i][j], 0.f);

    for (int ch = 0; ch < HID / 32; ch++) {
        int k0 = ch * 32;
#pragma unroll
        for (int p = 0; p < 2; p++) {
            int li = p * 256 + tid;
            int r = li >> 2, q = li & 3;
            uint4 vh = make_uint4(0u, 0u, 0u, 0u), vl = vh;
            if (r < rows) {
                size_t s = (size_t)(row0 + r) * HID + k0 + q * 8;
                vh = *reinterpret_cast<const uint4*>(&g_Hh[s]);
                vl = *reinterpret_cast<const uint4*>(&g_Hl[s]);
            }
            *reinterpret_cast<uint4*>(Ah + r * 40 + q * 8) = vh;
            *reinterpret_cast<uint4*>(Al + r * 40 + q * 8) = vl;
        }
#pragma unroll
        for (int p = 0; p < 4; p++) {
            int li = p * 256 + tid;
            int r = li >> 5, q = li & 31;
            float4 v = *reinterpret_cast<const float4*>(
                W2e + (size_t)(k0 + r) * DIM + n0 + q * 4);
            ull hp, lp; split4t(v, hp, lp);
            *reinterpret_cast<ull*>(Bh + r * 136 + q * 4) = hp;
            *reinterpret_cast<ull*>(Bl + r * 136 + q * 4) = lp;
        }
        __syncthreads();

#pragma unroll
        for (int ks = 0; ks < 2; ks++) {
            wmma::fragment<wmma::matrix_a, 16, 16, 16, __nv_bfloat16, wmma::row_major> af[2];
#pragma unroll
            for (int i = 0; i < 2; i++)
                wmma::load_matrix_sync(af[i], Ah + (wm * 32 + i * 16) * 40 + ks * 16, 40);
#pragma unroll
            for (int j = 0; j < 4; j++) {
                int bcol = wn * 64 + j * 16;
                wmma::fragment<wmma::matrix_b, 16, 16, 16, __nv_bfloat16, wmma::row_major> bf;
                wmma::load_matrix_sync(bf, Bh + ks * 16 * 136 + bcol, 136);
#pragma unroll
                for (int i = 0; i < 2; i++) wmma::mma_sync(acc[i][j], af[i], bf, acc[i][j]);
                wmma::load_matrix_sync(bf, Bl + ks * 16 * 136 + bcol, 136);
#pragma unroll
                for (int i = 0; i < 2; i++) wmma::mma_sync(acc[i][j], af[i], bf, acc[i][j]);
            }
#pragma unroll
            for (int i = 0; i < 2; i++)
                wmma::load_matrix_sync(af[i], Al + (wm * 32 + i * 16) * 40 + ks * 16, 40);
#pragma unroll
            for (int j = 0; j < 4; j++) {
                int bcol = wn * 64 + j * 16;
                wmma::fragment<wmma::matrix_b, 16, 16, 16, __nv_bfloat16, wmma::row_major> bf;
                wmma::load_matrix_sync(bf, Bh + ks * 16 * 136 + bcol, 136);
#pragma unroll
                for (int i = 0; i < 2; i++) wmma::mma_sync(acc[i][j], af[i], bf, acc[i][j]);
            }
        }
        __syncthreads();
    }

    if (rows == BM) {
#pragma unroll
        for (int i = 0; i < 2; i++)
#pragma unroll
            for (int j = 0; j < 4; j++)
                wmma::store_matrix_sync(
                    g_P + (size_t)(row0 + wm * 32 + i * 16) * DIM + n0 + wn * 64 + j * 16,
                    acc[i][j], DIM, wmma::mem_row_major);
    } else {
#pragma unroll
        for (int half = 0; half < 2; half++) {
            if (wn == half) {
#pragma unroll
                for (int i = 0; i < 2; i++)
#pragma unroll
                    for (int j = 0; j < 4; j++)
                        wmma::store_matrix_sync(stage + (wm * 32 + i * 16) * 72 + j * 16,
                                                acc[i][j], 72, wmma::mem_row_major);
            }
            __syncthreads();
            int row = tid >> 1, h2 = tid & 1;
            if (row < rows) {
                float* dst = g_P + (size_t)(row0 + row) * DIM + n0 + half * 64 + h2 * 32;
#pragma unroll
                for (int j = 0; j < 8; j++)
                    *reinterpret_cast<float4*>(dst + j * 4) =
                        *reinterpret_cast<const float4*>(stage + row * 72 + h2 * 32 + j * 4);
            }
            __syncthreads();
        }
    }
}

// ---------------- combine (verbatim) ------------------------------------------
__global__ void combine_kernel(float* __restrict__ out) {
    int t = blockIdx.x;
    int d = threadIdx.x * 4;
    int pb = t * 2;
    int r0 = g_pos[pb], r1 = g_pos[pb + 1];
    float g0 = g_gate[pb], g1 = g_gate[pb + 1];
    float4 v0 = *reinterpret_cast<const float4*>(g_P + (size_t)r0 * DIM + d);
    float4 v1 = *reinterpret_cast<const float4*>(g_P + (size_t)r1 * DIM + d);
    float4 o;
    o.x = g0 * v0.x + g1 * v1.x;
    o.y = g0 * v0.y + g1 * v1.y;
    o.z = g0 * v0.z + g1 * v1.z;
    o.w = g0 * v0.w + g1 * v1.w;
    *reinterpret_cast<float4*>(out + (size_t)t * DIM + d) = o;
}

// ---------------- launch ------------------------------------------------------
extern "C" void kernel_launch(void* const* d_in, const int* in_sizes, int n_in,
                              void* d_out, int out_size) {
    (void)in_sizes; (void)n_in; (void)out_size;
    const float* x  = (const float*)d_in[0];
    const float* Wr = (const float*)d_in[1];
    const float* W1 = (const float*)d_in[2];
    const float* W2 = (const float*)d_in[3];
    const float* W3 = (const float*)d_in[4];
    float* out = (float*)d_out;

    init_kernel<<<1, 32>>>();
    router_kernel<<<T_TOK / 8, 256>>>(x, Wr);
    scan_kernel<<<1, 1>>>();
    scatter_kernel<<<NP / 256, 256>>>();
    x_split_kernel<<<(T_TOK * DIM) / 1024, 256>>>(x);
    gemm1_wmma<<<dim3(MAXTILES, HID / 64), 256>>>(W1, W3);
    gemm2_wmma<<<dim3(MAXTILES, DIM / 128), 256>>>(W2);
    combine_kernel<<<T_TOK, 256>>>(out);
}